// round 15
// baseline (speedup 1.0000x reference)
#include <cuda.h>
#include <cuda_runtime.h>
#include <cuda_bf16.h>
#include <cuda_fp16.h>
#include <math.h>
#include <stdint.h>

// Problem constants
#define B_  128
#define T_  256
#define U2_ 1024
#define DA_ 512
#define R_  8
#define SC_ 128
#define OA_ 16
#define NR_ 3

// tcgen05 only exists in the arch-specific (sm_103a) compilation pass.
#if !defined(__CUDA_ARCH__) || defined(__CUDA_ARCH_FEAT_SM103_ALL)
#define TCG_OK 1
#else
#define TCG_OK 0
#endif

// Scratch in __device__ globals (allocation-free rule)
__device__ __half g_xh[(long)B_ * T_ * U2_];          // x fp16
__device__ __half g_w1h[(long)R_ * DA_ * U2_];        // WS1 fp16
__device__ __half g_w2h[(long)R_ * U2_ * DA_];        // WS2 fp16
__device__ __half g_hbar[(long)B_ * T_ * R_ * DA_];   // hbar fp16 [bt, r*DA+a]
__device__ float  g_m[(long)B_ * R_ * U2_];           // [b, r*U2+u]
__device__ float  g_votes[2L * B_ * R_ * SC_ * OA_];  // split-K partials
// Tensor maps: [0]=WS1(fp16,2D), [1]=WS2(fp16,3D)
__device__ __align__(128) unsigned char g_tmaps[2 * 128];

// ===========================================================================
// PTX helpers
// ===========================================================================
__device__ __forceinline__ uint32_t smem_u32(const void* p) {
    uint32_t a;
    asm("{ .reg .u64 t; cvta.to.shared.u64 t, %1; cvt.u32.u64 %0, t; }"
        : "=r"(a) : "l"(p));
    return a;
}

#define MBARRIER_INIT(addr, count) \
    asm volatile("mbarrier.init.shared.b64 [%0], %1;" \
                 :: "r"((uint32_t)(addr)), "r"((uint32_t)(count)) : "memory")

#define MBARRIER_EXPECT_TX(addr, bytes) \
    asm volatile("mbarrier.arrive.expect_tx.shared.b64 _, [%0], %1;" \
                 :: "r"((uint32_t)(addr)), "r"((uint32_t)(bytes)) : "memory")

#define MBARRIER_WAIT_PARITY(mbar_smem_addr, phase_parity) do { \
    uint32_t _mbar = (uint32_t)(mbar_smem_addr); \
    uint32_t _parity = (uint32_t)(phase_parity); \
    uint32_t _done; \
    asm volatile( \
        "{\n\t" \
        ".reg .pred p;\n\t" \
        "mbarrier.try_wait.parity.acquire.cta.shared::cta.b64 p, [%1], %2;\n\t" \
        "selp.b32 %0, 1, 0, p;\n\t" \
        "}" \
        : "=r"(_done) : "r"(_mbar), "r"(_parity) : "memory"); \
    if (!_done) { \
        asm volatile( \
            "{\n\t" \
            ".reg .pred P1;\n\t" \
            "WAIT_LOOP_%=:\n\t" \
            "mbarrier.try_wait.parity.acquire.cta.shared::cta.b64 P1, [%0], %1, 0x989680;\n\t" \
            "@P1 bra.uni WAIT_DONE_%=;\n\t" \
            "bra.uni WAIT_LOOP_%=;\n\t" \
            "WAIT_DONE_%=:\n\t" \
            "}" \
            :: "r"(_mbar), "r"(_parity) : "memory"); \
    } \
} while(0)

#if TCG_OK
#define TCGEN05_ALLOC(smem_result_addr, nCols) \
    asm volatile("tcgen05.alloc.cta_group::1.sync.aligned.shared::cta.b32 [%0], %1;" \
                 :: "r"((uint32_t)(smem_result_addr)), "r"((uint32_t)(nCols)) : "memory")
#define TCGEN05_DEALLOC(tmem_addr, nCols) \
    asm volatile("tcgen05.dealloc.cta_group::1.sync.aligned.b32 %0, %1;" \
                 :: "r"(tmem_addr), "r"((uint32_t)(nCols)))
#define TCGEN05_RELINQUISH() \
    asm volatile("tcgen05.relinquish_alloc_permit.cta_group::1.sync.aligned;")
#define TCGEN05_COMMIT(mbar) \
    asm volatile("tcgen05.commit.cta_group::1.mbarrier::arrive::one.shared::cluster.b64 [%0];" \
                 :: "r"((uint32_t)(mbar)) : "memory")
#define TCGEN05_WAIT_LD() \
    asm volatile("tcgen05.wait::ld.sync.aligned;" ::: "memory")
#define TCGEN05_FENCE_AFTER() \
    asm volatile("tcgen05.fence::after_thread_sync;" ::: "memory")
#define FENCE_PROXY_ASYNC() \
    asm volatile("fence.proxy.async.shared::cta;" ::: "memory")

#define TMA_2D(smem, tmap, cx, cy, mbar) \
    asm volatile("cp.async.bulk.tensor.2d.shared::cta.global.tile.mbarrier::complete_tx::bytes " \
                 "[%0], [%1, {%2, %3}], [%4];" \
                 :: "r"((uint32_t)(smem)), "l"(tmap), "r"((int)(cx)), "r"((int)(cy)), \
                    "r"((uint32_t)(mbar)) : "memory")
#define TMA_3D(smem, tmap, cx, cy, cz, mbar) \
    asm volatile("cp.async.bulk.tensor.3d.shared::cta.global.tile.mbarrier::complete_tx::bytes " \
                 "[%0], [%1, {%2, %3, %4}], [%5];" \
                 :: "r"((uint32_t)(smem)), "l"(tmap), "r"((int)(cx)), "r"((int)(cy)), \
                    "r"((int)(cz)), "r"((uint32_t)(mbar)) : "memory")

#define TCGEN05_LD_X32(r, tmem_addr) \
    asm volatile( \
        "tcgen05.ld.sync.aligned.32x32b.x32.b32 " \
        "{%0, %1, %2, %3, %4, %5, %6, %7, " \
        " %8, %9, %10, %11, %12, %13, %14, %15, " \
        " %16, %17, %18, %19, %20, %21, %22, %23, " \
        " %24, %25, %26, %27, %28, %29, %30, %31}, [%32];" \
        : "=r"((r)[0]),  "=r"((r)[1]),  "=r"((r)[2]),  "=r"((r)[3]), \
          "=r"((r)[4]),  "=r"((r)[5]),  "=r"((r)[6]),  "=r"((r)[7]), \
          "=r"((r)[8]),  "=r"((r)[9]),  "=r"((r)[10]), "=r"((r)[11]), \
          "=r"((r)[12]), "=r"((r)[13]), "=r"((r)[14]), "=r"((r)[15]), \
          "=r"((r)[16]), "=r"((r)[17]), "=r"((r)[18]), "=r"((r)[19]), \
          "=r"((r)[20]), "=r"((r)[21]), "=r"((r)[22]), "=r"((r)[23]), \
          "=r"((r)[24]), "=r"((r)[25]), "=r"((r)[26]), "=r"((r)[27]), \
          "=r"((r)[28]), "=r"((r)[29]), "=r"((r)[30]), "=r"((r)[31]) \
        : "r"(tmem_addr))

// f16 SS MMA, cta_group::1, fp32 accumulate
__device__ __forceinline__ void mma_f16_ss(uint32_t d_tmem, uint64_t a_desc,
                                           uint64_t b_desc, uint32_t idesc,
                                           uint32_t enable) {
    asm volatile(
        "{\n\t"
        ".reg .pred p;\n\t"
        "setp.ne.u32 p, %4, 0;\n\t"
        "tcgen05.mma.cta_group::1.kind::f16 [%0], %1, %2, %3, p;\n\t"
        "}"
        :: "r"(d_tmem), "l"(a_desc), "l"(b_desc), "r"(idesc), "r"(enable)
        : "memory");
}
#endif // TCG_OK

// SW128 K-major smem descriptor (version=1 Blackwell, LBO=1, SBO=64)
static constexpr uint64_t SMEM_DESC_BASE_SW128 =
    (uint64_t(2)  << 61) | (uint64_t(1) << 46) |
    (uint64_t(64) << 32) | (uint64_t(1) << 16);
#define MAKE_SMEM_DESC(base_addr) \
    (SMEM_DESC_BASE_SW128 | ((uint64_t)((base_addr) >> 4) & 0x3FFF))
#define SWZ128(off) ((off) ^ (((off) >> 3) & 0x70))

__device__ __forceinline__ void cp_async16(uint32_t dst, const void* src) {
    asm volatile("cp.async.cg.shared.global [%0], [%1], 16;"
                 :: "r"(dst), "l"(src) : "memory");
}
__device__ __forceinline__ void cp_async_arrive_noinc(uint32_t mbar) {
    asm volatile("cp.async.mbarrier.arrive.noinc.shared::cta.b64 [%0];"
                 :: "r"(mbar) : "memory");
}

// idesc f16: c=F32(1<<4), fp16 A/B, N=256 (32<<17), M=128 (8<<24)
static constexpr uint32_t IDESC_F16 =
    (1u << 4) | (32u << 17) | (8u << 24);

// ===========================================================================
// fp32 -> fp16 conversion (vectorized, 8 elems/thread)
// ===========================================================================
__global__ __launch_bounds__(256)
void f2h_kernel(const float* __restrict__ in, __half* __restrict__ out, long n)
{
    long i = ((long)blockIdx.x * blockDim.x + threadIdx.x) * 8;
    if (i >= n) return;
    float4 a = *reinterpret_cast<const float4*>(in + i);
    float4 b = *reinterpret_cast<const float4*>(in + i + 4);
    __half2 h0 = __floats2half2_rn(a.x, a.y);
    __half2 h1 = __floats2half2_rn(a.z, a.w);
    __half2 h2 = __floats2half2_rn(b.x, b.y);
    __half2 h3 = __floats2half2_rn(b.z, b.w);
    uint4 v;
    v.x = *reinterpret_cast<uint32_t*>(&h0);
    v.y = *reinterpret_cast<uint32_t*>(&h1);
    v.z = *reinterpret_cast<uint32_t*>(&h2);
    v.w = *reinterpret_cast<uint32_t*>(&h3);
    *reinterpret_cast<uint4*>(out + i) = v;
}

// ===========================================================================
// Stage A: f16 GEMM, tile 128x256x64, 2 CTAs/SM (R14 form, unchanged).
// ===========================================================================
#define A_NST 2
#define A_STAGE 49152
#define A_DSMEM (1024 + A_NST * A_STAGE)
#define A_FULL_CNT 257

__global__ __launch_bounds__(256, 2)
void gemm_a(const void* __restrict__ tmaps, const __half* __restrict__ Ag,
            __half* __restrict__ Cg)
{
#if TCG_OK
    constexpr int KT  = 16;
    constexpr int LDC = R_ * DA_;
    const void* tmw1 = (const unsigned char*)tmaps;

    extern __shared__ char dyn_smem[];
    __shared__ uint64_t bars[2 * A_NST + 1];
    __shared__ uint32_t tmem_slot;

    const int tid = threadIdx.x;
    const int n0 = blockIdx.x * 256;
    const int m0 = blockIdx.y * 128;

    const uint32_t raw = smem_u32(dyn_smem);
    const uint32_t tb = (raw + 1023u) & ~1023u;
    const uint32_t bar_base = smem_u32(&bars[0]);
    const uint32_t full0  = bar_base;
    const uint32_t empty0 = bar_base + A_NST * 8;
    const uint32_t doneb  = bar_base + 2 * A_NST * 8;

    if (tid == 0) {
#pragma unroll
        for (int s = 0; s < A_NST; s++) {
            MBARRIER_INIT(full0 + s * 8, A_FULL_CNT);
            MBARRIER_INIT(empty0 + s * 8, 1);
        }
        MBARRIER_INIT(doneb, 1);
    }
    if ((tid >> 5) == 0) {
        TCGEN05_ALLOC(smem_u32(&tmem_slot), 256);
        TCGEN05_RELINQUISH();
    }
    __syncthreads();

    uint32_t tmem_base;
    asm volatile("ld.shared.b32 %0, [%1];" : "=r"(tmem_base)
                 : "r"(smem_u32(&tmem_slot)));

    uint32_t offA[4];
    const __half* aPtr[4];
#pragma unroll
    for (int i = 0; i < 4; i++) {
        int c = tid + i * 256;
        int row = c >> 3;
        int ci = c & 7;
        offA[i] = SWZ128((uint32_t)(row * 128 + ci * 16));
        aPtr[i] = Ag + (size_t)(m0 + row) * U2_ + ci * 8;
    }

    int prod_ph = 1, cons_ph = 0;

    for (int it = 0; it < KT + A_NST - 1; ++it) {
        if (it < KT) {
            const int s = it % A_NST;
            MBARRIER_WAIT_PARITY(empty0 + s * 8, prod_ph);
            const uint32_t aS = tb + s * A_STAGE;
            const uint32_t bS = aS + 16384;
            const int kbase = it * 64;
            if (tid == 0) {
                MBARRIER_EXPECT_TX(full0 + s * 8, 32768u);
                TMA_2D(bS, tmw1, kbase, n0, full0 + s * 8);
            }
#pragma unroll
            for (int i = 0; i < 4; i++)
                cp_async16(aS + offA[i], aPtr[i] + kbase);
            cp_async_arrive_noinc(full0 + s * 8);
            if (s == A_NST - 1) prod_ph ^= 1;
        }
        const int ck = it - (A_NST - 1);
        if (ck >= 0 && tid == 0) {
            const int s = ck % A_NST;
            MBARRIER_WAIT_PARITY(full0 + s * 8, cons_ph);
            FENCE_PROXY_ASYNC();
            const uint32_t aS = tb + s * A_STAGE;
            const uint32_t bS = aS + 16384;
            uint64_t ad = MAKE_SMEM_DESC(aS);
            uint64_t bd = MAKE_SMEM_DESC(bS);
#pragma unroll
            for (int ks = 0; ks < 4; ks++) {
                uint32_t en = (ck > 0 || ks > 0) ? 1u : 0u;
                mma_f16_ss(tmem_base, ad + 2 * ks, bd + 2 * ks, IDESC_F16, en);
            }
            TCGEN05_COMMIT(empty0 + s * 8);
            if (s == A_NST - 1) cons_ph ^= 1;
        }
    }
    if (tid == 0) TCGEN05_COMMIT(doneb);

    MBARRIER_WAIT_PARITY(doneb, 0);
    TCGEN05_FENCE_AFTER();

    const int w = tid >> 5, lane = tid & 31;
    const int half = w >> 2, sub = w & 3;
    const int mrow = m0 + sub * 32 + lane;
    __half* crow = Cg + (size_t)mrow * LDC + n0 + half * 128;

#pragma unroll
    for (int ch = 0; ch < 4; ch++) {
        uint32_t rr[32];
        TCGEN05_LD_X32(rr, tmem_base + half * 128 + ch * 32);
        TCGEN05_WAIT_LD();
        uint32_t hp[16];
#pragma unroll
        for (int j = 0; j < 16; j++) {
            float f0 = fmaxf(__uint_as_float(rr[2 * j]), 0.f);
            float f1 = fmaxf(__uint_as_float(rr[2 * j + 1]), 0.f);
            __half2 h = __floats2half2_rn(f0, f1);
            hp[j] = *reinterpret_cast<uint32_t*>(&h);
        }
#pragma unroll
        for (int q = 0; q < 4; q++) {
            uint4 v = make_uint4(hp[4 * q], hp[4 * q + 1],
                                 hp[4 * q + 2], hp[4 * q + 3]);
            *reinterpret_cast<uint4*>(crow + ch * 32 + q * 8) = v;
        }
    }

    __syncthreads();
    if ((tid >> 5) == 0) {
        TCGEN05_DEALLOC(tmem_base, 256);
    }
#endif
}

// ===========================================================================
// Fused stage B + C: tile u=256 x t=256, 1 CTA/SM, NST=3 (64KB stages).
//   A = WS2 (TMA 3D box 64x256, 32KB); B = hbar (cp.async, 8 chunks/thread).
//   scoresT[u,t] = WS2_r[u,:] @ hbar_{b,r}[t,:]^T  (two M=128 halves)
//   m[b,r,u] = softmax-weighted sum against xh; each thread owns one u row.
// ===========================================================================
#define BC_NST 3
#define BC_STAGE 65536
#define BC_DSMEM (1024 + BC_NST * BC_STAGE)
#define BC_FULL_CNT 257

__global__ __launch_bounds__(256, 1)
void gemm_bc(const void* __restrict__ tmaps, const __half* __restrict__ hbar,
             const __half* __restrict__ xh, float* __restrict__ mout)
{
#if TCG_OK
    constexpr int KT  = 8;
    constexpr int LDH = R_ * DA_;
    const void* tmw2 = (const unsigned char*)tmaps + 128;

    extern __shared__ char dyn_smem[];
    __shared__ uint64_t bars[2 * BC_NST + 1];
    __shared__ uint32_t tmem_slot;

    const int tid = threadIdx.x;
    const int n0 = blockIdx.x * 256;   // u chunk
    const int b  = blockIdx.y;
    const int z  = blockIdx.z;         // r
    const int t0 = b * T_;

    const uint32_t raw = smem_u32(dyn_smem);
    const uint32_t tb = (raw + 1023u) & ~1023u;
    const uint32_t bar_base = smem_u32(&bars[0]);
    const uint32_t full0  = bar_base;
    const uint32_t empty0 = bar_base + BC_NST * 8;
    const uint32_t doneb  = bar_base + 2 * BC_NST * 8;

    if (tid == 0) {
#pragma unroll
        for (int s = 0; s < BC_NST; s++) {
            MBARRIER_INIT(full0 + s * 8, BC_FULL_CNT);
            MBARRIER_INIT(empty0 + s * 8, 1);
        }
        MBARRIER_INIT(doneb, 1);
    }
    if ((tid >> 5) == 0) {
        TCGEN05_ALLOC(smem_u32(&tmem_slot), 512);
        TCGEN05_RELINQUISH();
    }
    __syncthreads();

    uint32_t tmem_base;
    asm volatile("ld.shared.b32 %0, [%1];" : "=r"(tmem_base)
                 : "r"(smem_u32(&tmem_slot)));

    // Hoisted k-invariant producer addressing (hbar t rows)
    uint32_t offB[8];
    const __half* bPtr[8];
#pragma unroll
    for (int i = 0; i < 8; i++) {
        int c = tid + i * 256;
        int row = c >> 3;
        int ci = c & 7;
        offB[i] = SWZ128((uint32_t)(row * 128 + ci * 16));
        bPtr[i] = hbar + (size_t)(t0 + row) * LDH + z * DA_ + ci * 8;
    }

    int prod_ph = 1, cons_ph = 0;

    for (int it = 0; it < KT + BC_NST - 1; ++it) {
        if (it < KT) {
            const int s = it % BC_NST;
            MBARRIER_WAIT_PARITY(empty0 + s * 8, prod_ph);
            const uint32_t aS = tb + s * BC_STAGE;
            const uint32_t bS = aS + 32768;
            const int kbase = it * 64;
            if (tid == 0) {
                MBARRIER_EXPECT_TX(full0 + s * 8, 32768u);
                TMA_3D(aS, tmw2, kbase, n0, z, full0 + s * 8);
            }
#pragma unroll
            for (int i = 0; i < 8; i++)
                cp_async16(bS + offB[i], bPtr[i] + kbase);
            cp_async_arrive_noinc(full0 + s * 8);
            if (s == BC_NST - 1) prod_ph ^= 1;
        }
        const int ck = it - (BC_NST - 1);
        if (ck >= 0 && tid == 0) {
            const int s = ck % BC_NST;
            MBARRIER_WAIT_PARITY(full0 + s * 8, cons_ph);
            FENCE_PROXY_ASYNC();
            const uint32_t aS = tb + s * BC_STAGE;
            const uint32_t bS = aS + 32768;
            uint64_t ad0 = MAKE_SMEM_DESC(aS);
            uint64_t ad1 = MAKE_SMEM_DESC(aS + 16384);
            uint64_t bd  = MAKE_SMEM_DESC(bS);
#pragma unroll
            for (int ks = 0; ks < 4; ks++) {
                uint32_t en = (ck > 0 || ks > 0) ? 1u : 0u;
                mma_f16_ss(tmem_base,       ad0 + 2 * ks, bd + 2 * ks, IDESC_F16, en);
                mma_f16_ss(tmem_base + 256, ad1 + 2 * ks, bd + 2 * ks, IDESC_F16, en);
            }
            TCGEN05_COMMIT(empty0 + s * 8);
            if (s == BC_NST - 1) cons_ph ^= 1;
        }
    }
    if (tid == 0) TCGEN05_COMMIT(doneb);

    MBARRIER_WAIT_PARITY(doneb, 0);
    TCGEN05_FENCE_AFTER();

    // ---- register softmax-weighted-sum epilogue (full t range per thread) -
    const int w = tid >> 5, lane = tid & 31;
    const int half = w >> 2, sub = w & 3;
    const int urow = half * 128 + sub * 32 + lane;   // 0..255
    const int ug   = n0 + urow;
    const uint32_t dbase = tmem_base + half * 256;

    const __half* xp = xh + (size_t)b * T_ * U2_ + ug;   // stride U2_ over t

    float mx = -3.4e38f, Z = 0.f, W = 0.f;
#pragma unroll
    for (int ch = 0; ch < 8; ch++) {
        uint32_t rr[32];
        TCGEN05_LD_X32(rr, dbase + ch * 32);
        TCGEN05_WAIT_LD();

        float s[32];
        float cmx = -3.4e38f;
#pragma unroll
        for (int j = 0; j < 32; j++) {
            s[j] = __uint_as_float(rr[j]);
            cmx = fmaxf(cmx, s[j]);
        }
        float nm = fmaxf(mx, cmx);
        float resc = __expf(mx - nm);
        Z *= resc;
        W *= resc;
#pragma unroll
        for (int j = 0; j < 32; j++) {
            float e = __expf(s[j] - nm);
            Z += e;
            W = fmaf(e, __half2float(xp[(size_t)(ch * 32 + j) * U2_]), W);
        }
        mx = nm;
    }
    mout[((size_t)b * R_ + z) * U2_ + ug] = W / Z;

    __syncthreads();
    if ((tid >> 5) == 0) {
        TCGEN05_DEALLOC(tmem_base, 512);
    }
#endif
}

// ===========================================================================
// Stage D (split-K): votes partial = m_r slice @ CW_r slice. grid (32,2,8).
// ===========================================================================
__global__ __launch_bounds__(256)
void sgemm_d(const float* __restrict__ Ag, const float* __restrict__ Bg,
             float* __restrict__ Cg)
{
    const int n0 = blockIdx.x * 64;
    const int kh = blockIdx.y;
    const int z  = blockIdx.z;
    const int kbeg = kh * 512;

    __shared__ float As[32][128 + 4];
    __shared__ float Bs[32][64 + 4];

    const int tid = threadIdx.x;
    const int tx = tid & 15;
    const int ty = tid >> 4;

    float acc[8][4];
#pragma unroll
    for (int i = 0; i < 8; i++)
#pragma unroll
        for (int j = 0; j < 4; j++) acc[i][j] = 0.f;

    for (int k0 = kbeg; k0 < kbeg + 512; k0 += 32) {
#pragma unroll
        for (int i = 0; i < 4; i++) {
            int f = tid + i * 256;
            int row = f >> 3;
            int kk = (f & 7) << 2;
            float4 v = *reinterpret_cast<const float4*>(
                Ag + (size_t)row * (R_ * U2_) + z * U2_ + k0 + kk);
            As[kk + 0][row] = v.x;
            As[kk + 1][row] = v.y;
            As[kk + 2][row] = v.z;
            As[kk + 3][row] = v.w;
        }
#pragma unroll
        for (int i = 0; i < 2; i++) {
            int f = tid + i * 256;
            int kr = f >> 4;
            int nn = (f & 15) << 2;
            float4 v = *reinterpret_cast<const float4*>(
                Bg + ((size_t)z * U2_ + k0 + kr) * (SC_ * OA_) + n0 + nn);
            *reinterpret_cast<float4*>(&Bs[kr][nn]) = v;
        }
        __syncthreads();

#pragma unroll
        for (int k = 0; k < 32; k++) {
            float a[8], bb[4];
            *reinterpret_cast<float4*>(&a[0]) =
                *reinterpret_cast<const float4*>(&As[k][ty * 8]);
            *reinterpret_cast<float4*>(&a[4]) =
                *reinterpret_cast<const float4*>(&As[k][ty * 8 + 4]);
            *reinterpret_cast<float4*>(&bb[0]) =
                *reinterpret_cast<const float4*>(&Bs[k][tx * 4]);
#pragma unroll
            for (int i = 0; i < 8; i++)
#pragma unroll
                for (int j = 0; j < 4; j++)
                    acc[i][j] = fmaf(a[i], bb[j], acc[i][j]);
        }
        __syncthreads();
    }

    float* out = Cg + (size_t)kh * B_ * R_ * SC_ * OA_;
#pragma unroll
    for (int i = 0; i < 8; i++) {
        size_t row = ty * 8 + i;
        float4 v = make_float4(acc[i][0], acc[i][1], acc[i][2], acc[i][3]);
        *reinterpret_cast<float4*>(
            out + row * (R_ * SC_ * OA_) + z * (SC_ * OA_) + n0 + tx * 4) = v;
    }
}

// ===========================================================================
// Stage E: dynamic routing (reads the two split-K vote partials).
// ===========================================================================
__global__ __launch_bounds__(256)
void routing_kernel(const float* __restrict__ votes, float* __restrict__ out)
{
    const int b = blockIdx.x;
    const int tid = threadIdx.x;
    const size_t vstride = (size_t)B_ * R_ * SC_ * OA_;
    const float* vb  = votes + (size_t)b * R_ * SC_ * OA_;
    const float* vb2 = vb + vstride;

    __shared__ float logits[R_][SC_];
    __shared__ float route[R_][SC_];
    __shared__ float act[SC_ * OA_];
    __shared__ float fac[SC_];

    for (int i = tid; i < R_ * SC_; i += 256)
        (&logits[0][0])[i] = 0.f;
    __syncthreads();

    for (int it = 0; it < NR_; it++) {
        int w = tid >> 5, lane = tid & 31;
        if (w < R_) {
            float v0 = logits[w][lane];
            float v1 = logits[w][lane + 32];
            float v2 = logits[w][lane + 64];
            float v3 = logits[w][lane + 96];
            float mx = fmaxf(fmaxf(v0, v1), fmaxf(v2, v3));
#pragma unroll
            for (int off = 16; off; off >>= 1)
                mx = fmaxf(mx, __shfl_xor_sync(0xFFFFFFFFu, mx, off));
            float e0 = expf(v0 - mx), e1 = expf(v1 - mx);
            float e2 = expf(v2 - mx), e3 = expf(v3 - mx);
            float s = e0 + e1 + e2 + e3;
#pragma unroll
            for (int off = 16; off; off >>= 1)
                s += __shfl_xor_sync(0xFFFFFFFFu, s, off);
            float inv = 1.f / s;
            route[w][lane]      = e0 * inv;
            route[w][lane + 32] = e1 * inv;
            route[w][lane + 64] = e2 * inv;
            route[w][lane + 96] = e3 * inv;
        }
        __syncthreads();

        for (int idx = tid; idx < SC_ * OA_; idx += 256) {
            int c = idx >> 4, o = idx & 15;
            float s = 0.f;
#pragma unroll
            for (int r = 0; r < R_; r++) {
                size_t vi = ((size_t)r * SC_ + c) * OA_ + o;
                s = fmaf(route[r][c], vb[vi] + vb2[vi], s);
            }
            act[idx] = s;
        }
        __syncthreads();

        if (tid < SC_) {
            float n2 = 0.f;
#pragma unroll
            for (int o = 0; o < OA_; o++) {
                float v = act[tid * OA_ + o];
                n2 = fmaf(v, v, n2);
            }
            fac[tid] = sqrtf(n2) / (1.f + n2);
        }
        __syncthreads();
        for (int idx = tid; idx < SC_ * OA_; idx += 256)
            act[idx] *= fac[idx >> 4];
        __syncthreads();

        if (it < NR_ - 1) {
            for (int idx = tid; idx < R_ * SC_; idx += 256) {
                int r = idx >> 7, c = idx & 127;
                float d = 0.f;
#pragma unroll
                for (int o = 0; o < OA_; o++) {
                    size_t vi = ((size_t)r * SC_ + c) * OA_ + o;
                    d = fmaf(vb[vi] + vb2[vi], act[c * OA_ + o], d);
                }
                logits[r][c] += d;
            }
            __syncthreads();
        }
    }

    if (tid < SC_) {
        float n2 = 0.f;
#pragma unroll
        for (int o = 0; o < OA_; o++) {
            float v = act[tid * OA_ + o];
            n2 = fmaf(v, v, n2);
        }
        out[(long)b * SC_ + tid] = sqrtf(n2);
    }
}

// ===========================================================================
// Host: tensor-map construction (driver entry point; no -lcuda link needed)
// ===========================================================================
typedef CUresult (CUDAAPI *PFN_encodeTiled)(
    CUtensorMap*, CUtensorMapDataType, cuuint32_t, void*,
    const cuuint64_t*, const cuuint64_t*, const cuuint32_t*, const cuuint32_t*,
    CUtensorMapInterleave, CUtensorMapSwizzle, CUtensorMapL2promotion,
    CUtensorMapFloatOOBfill);

extern "C" void kernel_launch(void* const* d_in, const int* in_sizes, int n_in,
                              void* d_out, int out_size)
{
    const float* x   = (const float*)d_in[0];  // [B,T,U2]
    const float* WS1 = (const float*)d_in[1];  // [R,DA,U2]
    const float* WS2 = (const float*)d_in[2];  // [R,U2,DA]
    const float* CW  = (const float*)d_in[3];  // [R,U2,SC*OA]
    float* out = (float*)d_out;                // [B,SC]

    __half *xh, *w1h, *w2h, *hbar;
    float *m, *votes;
    unsigned char* dtm;
    cudaGetSymbolAddress((void**)&xh,    g_xh);
    cudaGetSymbolAddress((void**)&w1h,   g_w1h);
    cudaGetSymbolAddress((void**)&w2h,   g_w2h);
    cudaGetSymbolAddress((void**)&hbar,  g_hbar);
    cudaGetSymbolAddress((void**)&m,     g_m);
    cudaGetSymbolAddress((void**)&votes, g_votes);
    cudaGetSymbolAddress((void**)&dtm,   g_tmaps);

    // Tensor maps (deterministic; same every call).
    PFN_encodeTiled enc = nullptr;
    cudaDriverEntryPointQueryResult qr;
    cudaGetDriverEntryPoint("cuTensorMapEncodeTiled", (void**)&enc,
                            cudaEnableDefault, &qr);
    static CUtensorMap h_tm[2];
    // [0] WS1 fp16: 2D [U2 cols, R*DA rows], box 64x256, SW128
    {
        cuuint64_t dims[2] = {U2_, (uint64_t)R_ * DA_};
        cuuint64_t strides[1] = {(uint64_t)U2_ * 2};
        cuuint32_t box[2] = {64, 256};
        cuuint32_t es[2] = {1, 1};
        enc(&h_tm[0], CU_TENSOR_MAP_DATA_TYPE_FLOAT16, 2, (void*)w1h,
            dims, strides, box, es,
            CU_TENSOR_MAP_INTERLEAVE_NONE, CU_TENSOR_MAP_SWIZZLE_128B,
            CU_TENSOR_MAP_L2_PROMOTION_L2_128B,
            CU_TENSOR_MAP_FLOAT_OOB_FILL_NONE);
    }
    // [1] WS2 fp16: 3D [DA cols, U2 rows, R planes], box 64x256x1, SW128
    {
        cuuint64_t dims[3] = {DA_, U2_, R_};
        cuuint64_t strides[2] = {(uint64_t)DA_ * 2, (uint64_t)U2_ * DA_ * 2};
        cuuint32_t box[3] = {64, 256, 1};
        cuuint32_t es[3] = {1, 1, 1};
        enc(&h_tm[1], CU_TENSOR_MAP_DATA_TYPE_FLOAT16, 3, (void*)w2h,
            dims, strides, box, es,
            CU_TENSOR_MAP_INTERLEAVE_NONE, CU_TENSOR_MAP_SWIZZLE_128B,
            CU_TENSOR_MAP_L2_PROMOTION_L2_128B,
            CU_TENSOR_MAP_FLOAT_OOB_FILL_NONE);
    }
    cudaMemcpyAsync(dtm, h_tm, sizeof(h_tm), cudaMemcpyHostToDevice, 0);

    cudaFuncSetAttribute(gemm_a,
                         cudaFuncAttributeMaxDynamicSharedMemorySize, A_DSMEM);
    cudaFuncSetAttribute(gemm_bc,
                         cudaFuncAttributeMaxDynamicSharedMemorySize, BC_DSMEM);

    // Convert inputs to fp16
    {
        long nx = (long)B_ * T_ * U2_;
        long n1 = (long)R_ * DA_ * U2_;
        long n2 = (long)R_ * U2_ * DA_;
        f2h_kernel<<<(unsigned)((nx / 8 + 255) / 256), 256>>>(x, xh, nx);
        f2h_kernel<<<(unsigned)((n1 / 8 + 255) / 256), 256>>>(WS1, w1h, n1);
        f2h_kernel<<<(unsigned)((n2 / 8 + 255) / 256), 256>>>(WS2, w2h, n2);
    }

    // Stage A: hbar = relu(x @ WS1^T)  (f16; tile 128x256, 2 CTAs/SM)
    {
        dim3 grid((R_ * DA_) / 256, (B_ * T_) / 128, 1);   // (16, 256)
        gemm_a<<<grid, 256, A_DSMEM>>>(dtm, xh, hbar);
    }

    // Fused B+C: tile u=256 x t=256, 1 CTA/SM, NST=3.
    {
        dim3 grid(U2_ / 256, B_, R_);                      // (4, 128, 8)
        gemm_bc<<<grid, 256, BC_DSMEM>>>(dtm, hbar, xh, m);
    }

    // Stage D: split-K votes partials (fp32), grid (32, 2, 8)
    {
        dim3 grid((SC_ * OA_) / 64, 2, R_);
        sgemm_d<<<grid, 256>>>(m, CW, votes);
    }

    // Stage E: dynamic routing + final class logits
    routing_kernel<<<B_, 256>>>(votes, out);
}

// round 16
// speedup vs baseline: 1.1298x; 1.1298x over previous
#include <cuda.h>
#include <cuda_runtime.h>
#include <cuda_bf16.h>
#include <cuda_fp16.h>
#include <math.h>
#include <stdint.h>

// Problem constants
#define B_  128
#define T_  256
#define U2_ 1024
#define DA_ 512
#define R_  8
#define SC_ 128
#define OA_ 16
#define NR_ 3

// tcgen05 only exists in the arch-specific (sm_103a) compilation pass.
#if !defined(__CUDA_ARCH__) || defined(__CUDA_ARCH_FEAT_SM103_ALL)
#define TCG_OK 1
#else
#define TCG_OK 0
#endif

// Scratch in __device__ globals (allocation-free rule)
__device__ __half g_xh[(long)B_ * T_ * U2_];          // x fp16
__device__ __half g_w1h[(long)R_ * DA_ * U2_];        // WS1 fp16
__device__ __half g_w2h[(long)R_ * U2_ * DA_];        // WS2 fp16
__device__ __half g_hbar[(long)B_ * T_ * R_ * DA_];   // hbar fp16 [bt, r*DA+a]
__device__ float  g_m[(long)B_ * R_ * U2_];           // [b, r*U2+u]
__device__ float  g_votes[2L * B_ * R_ * SC_ * OA_];  // split-K partials
// Tensor maps: [0]=WS1(fp16,2D), [1]=WS2(fp16,3D)
__device__ __align__(128) unsigned char g_tmaps[2 * 128];

// ===========================================================================
// PTX helpers
// ===========================================================================
__device__ __forceinline__ uint32_t smem_u32(const void* p) {
    uint32_t a;
    asm("{ .reg .u64 t; cvta.to.shared.u64 t, %1; cvt.u32.u64 %0, t; }"
        : "=r"(a) : "l"(p));
    return a;
}

#define MBARRIER_INIT(addr, count) \
    asm volatile("mbarrier.init.shared.b64 [%0], %1;" \
                 :: "r"((uint32_t)(addr)), "r"((uint32_t)(count)) : "memory")

#define MBARRIER_EXPECT_TX(addr, bytes) \
    asm volatile("mbarrier.arrive.expect_tx.shared.b64 _, [%0], %1;" \
                 :: "r"((uint32_t)(addr)), "r"((uint32_t)(bytes)) : "memory")

#define MBARRIER_WAIT_PARITY(mbar_smem_addr, phase_parity) do { \
    uint32_t _mbar = (uint32_t)(mbar_smem_addr); \
    uint32_t _parity = (uint32_t)(phase_parity); \
    uint32_t _done; \
    asm volatile( \
        "{\n\t" \
        ".reg .pred p;\n\t" \
        "mbarrier.try_wait.parity.acquire.cta.shared::cta.b64 p, [%1], %2;\n\t" \
        "selp.b32 %0, 1, 0, p;\n\t" \
        "}" \
        : "=r"(_done) : "r"(_mbar), "r"(_parity) : "memory"); \
    if (!_done) { \
        asm volatile( \
            "{\n\t" \
            ".reg .pred P1;\n\t" \
            "WAIT_LOOP_%=:\n\t" \
            "mbarrier.try_wait.parity.acquire.cta.shared::cta.b64 P1, [%0], %1, 0x989680;\n\t" \
            "@P1 bra.uni WAIT_DONE_%=;\n\t" \
            "bra.uni WAIT_LOOP_%=;\n\t" \
            "WAIT_DONE_%=:\n\t" \
            "}" \
            :: "r"(_mbar), "r"(_parity) : "memory"); \
    } \
} while(0)

#if TCG_OK
#define TCGEN05_ALLOC(smem_result_addr, nCols) \
    asm volatile("tcgen05.alloc.cta_group::1.sync.aligned.shared::cta.b32 [%0], %1;" \
                 :: "r"((uint32_t)(smem_result_addr)), "r"((uint32_t)(nCols)) : "memory")
#define TCGEN05_DEALLOC(tmem_addr, nCols) \
    asm volatile("tcgen05.dealloc.cta_group::1.sync.aligned.b32 %0, %1;" \
                 :: "r"(tmem_addr), "r"((uint32_t)(nCols)))
#define TCGEN05_RELINQUISH() \
    asm volatile("tcgen05.relinquish_alloc_permit.cta_group::1.sync.aligned;")
#define TCGEN05_COMMIT(mbar) \
    asm volatile("tcgen05.commit.cta_group::1.mbarrier::arrive::one.shared::cluster.b64 [%0];" \
                 :: "r"((uint32_t)(mbar)) : "memory")
#define TCGEN05_WAIT_LD() \
    asm volatile("tcgen05.wait::ld.sync.aligned;" ::: "memory")
#define TCGEN05_FENCE_AFTER() \
    asm volatile("tcgen05.fence::after_thread_sync;" ::: "memory")
#define FENCE_PROXY_ASYNC() \
    asm volatile("fence.proxy.async.shared::cta;" ::: "memory")

#define TMA_2D(smem, tmap, cx, cy, mbar) \
    asm volatile("cp.async.bulk.tensor.2d.shared::cta.global.tile.mbarrier::complete_tx::bytes " \
                 "[%0], [%1, {%2, %3}], [%4];" \
                 :: "r"((uint32_t)(smem)), "l"(tmap), "r"((int)(cx)), "r"((int)(cy)), \
                    "r"((uint32_t)(mbar)) : "memory")
#define TMA_3D(smem, tmap, cx, cy, cz, mbar) \
    asm volatile("cp.async.bulk.tensor.3d.shared::cta.global.tile.mbarrier::complete_tx::bytes " \
                 "[%0], [%1, {%2, %3, %4}], [%5];" \
                 :: "r"((uint32_t)(smem)), "l"(tmap), "r"((int)(cx)), "r"((int)(cy)), \
                    "r"((int)(cz)), "r"((uint32_t)(mbar)) : "memory")

#define TCGEN05_LD_X32(r, tmem_addr) \
    asm volatile( \
        "tcgen05.ld.sync.aligned.32x32b.x32.b32 " \
        "{%0, %1, %2, %3, %4, %5, %6, %7, " \
        " %8, %9, %10, %11, %12, %13, %14, %15, " \
        " %16, %17, %18, %19, %20, %21, %22, %23, " \
        " %24, %25, %26, %27, %28, %29, %30, %31}, [%32];" \
        : "=r"((r)[0]),  "=r"((r)[1]),  "=r"((r)[2]),  "=r"((r)[3]), \
          "=r"((r)[4]),  "=r"((r)[5]),  "=r"((r)[6]),  "=r"((r)[7]), \
          "=r"((r)[8]),  "=r"((r)[9]),  "=r"((r)[10]), "=r"((r)[11]), \
          "=r"((r)[12]), "=r"((r)[13]), "=r"((r)[14]), "=r"((r)[15]), \
          "=r"((r)[16]), "=r"((r)[17]), "=r"((r)[18]), "=r"((r)[19]), \
          "=r"((r)[20]), "=r"((r)[21]), "=r"((r)[22]), "=r"((r)[23]), \
          "=r"((r)[24]), "=r"((r)[25]), "=r"((r)[26]), "=r"((r)[27]), \
          "=r"((r)[28]), "=r"((r)[29]), "=r"((r)[30]), "=r"((r)[31]) \
        : "r"(tmem_addr))

// f16 SS MMA, cta_group::1, fp32 accumulate
__device__ __forceinline__ void mma_f16_ss(uint32_t d_tmem, uint64_t a_desc,
                                           uint64_t b_desc, uint32_t idesc,
                                           uint32_t enable) {
    asm volatile(
        "{\n\t"
        ".reg .pred p;\n\t"
        "setp.ne.u32 p, %4, 0;\n\t"
        "tcgen05.mma.cta_group::1.kind::f16 [%0], %1, %2, %3, p;\n\t"
        "}"
        :: "r"(d_tmem), "l"(a_desc), "l"(b_desc), "r"(idesc), "r"(enable)
        : "memory");
}
#endif // TCG_OK

// SW128 K-major smem descriptor (version=1 Blackwell, LBO=1, SBO=64)
static constexpr uint64_t SMEM_DESC_BASE_SW128 =
    (uint64_t(2)  << 61) | (uint64_t(1) << 46) |
    (uint64_t(64) << 32) | (uint64_t(1) << 16);
#define MAKE_SMEM_DESC(base_addr) \
    (SMEM_DESC_BASE_SW128 | ((uint64_t)((base_addr) >> 4) & 0x3FFF))
#define SWZ128(off) ((off) ^ (((off) >> 3) & 0x70))

__device__ __forceinline__ void cp_async16(uint32_t dst, const void* src) {
    asm volatile("cp.async.cg.shared.global [%0], [%1], 16;"
                 :: "r"(dst), "l"(src) : "memory");
}
__device__ __forceinline__ void cp_async_arrive_noinc(uint32_t mbar) {
    asm volatile("cp.async.mbarrier.arrive.noinc.shared::cta.b64 [%0];"
                 :: "r"(mbar) : "memory");
}

// ===========================================================================
// Pipeline config: tile M=128 x N=256, stage 48KB (A 16KB + B 32KB), NST=2,
// 2 CTAs/SM. full arrivals: 256 cp.async + 1 expect_tx = 257.
// ===========================================================================
#define NST 2
#define STAGE_BYTES 49152
#define GEMM_DSMEM (1024 + NST * STAGE_BYTES)
#define FULL_CNT 257

// idesc f16: c=F32(1<<4), fp16 A/B, N=256 (32<<17), M=128 (8<<24)
static constexpr uint32_t IDESC_F16 =
    (1u << 4) | (32u << 17) | (8u << 24);

// ===========================================================================
// fp32 -> fp16 conversion (vectorized, 8 elems/thread)
// ===========================================================================
__global__ __launch_bounds__(256)
void f2h_kernel(const float* __restrict__ in, __half* __restrict__ out, long n)
{
    long i = ((long)blockIdx.x * blockDim.x + threadIdx.x) * 8;
    if (i >= n) return;
    float4 a = *reinterpret_cast<const float4*>(in + i);
    float4 b = *reinterpret_cast<const float4*>(in + i + 4);
    __half2 h0 = __floats2half2_rn(a.x, a.y);
    __half2 h1 = __floats2half2_rn(a.z, a.w);
    __half2 h2 = __floats2half2_rn(b.x, b.y);
    __half2 h3 = __floats2half2_rn(b.z, b.w);
    uint4 v;
    v.x = *reinterpret_cast<uint32_t*>(&h0);
    v.y = *reinterpret_cast<uint32_t*>(&h1);
    v.z = *reinterpret_cast<uint32_t*>(&h2);
    v.w = *reinterpret_cast<uint32_t*>(&h3);
    *reinterpret_cast<uint4*>(out + i) = v;
}

// ===========================================================================
// Stage A: f16 GEMM, tile 128x256x64, 2 CTAs/SM (hoisted producer offsets).
// A = x (cp.async); B = WS1 (TMA box 64x256). hbar = relu(x @ WS1^T), fp16.
// ===========================================================================
__global__ __launch_bounds__(256, 2)
void gemm_a(const void* __restrict__ tmaps, const __half* __restrict__ Ag,
            __half* __restrict__ Cg)
{
#if TCG_OK
    constexpr int KT  = 16;
    constexpr int LDC = R_ * DA_;
    const void* tmw1 = (const unsigned char*)tmaps;

    extern __shared__ char dyn_smem[];
    __shared__ uint64_t bars[2 * NST + 1];
    __shared__ uint32_t tmem_slot;

    const int tid = threadIdx.x;
    const int n0 = blockIdx.x * 256;
    const int m0 = blockIdx.y * 128;

    const uint32_t raw = smem_u32(dyn_smem);
    const uint32_t tb = (raw + 1023u) & ~1023u;
    const uint32_t bar_base = smem_u32(&bars[0]);
    const uint32_t full0  = bar_base;
    const uint32_t empty0 = bar_base + NST * 8;
    const uint32_t doneb  = bar_base + 2 * NST * 8;

    if (tid == 0) {
#pragma unroll
        for (int s = 0; s < NST; s++) {
            MBARRIER_INIT(full0 + s * 8, FULL_CNT);
            MBARRIER_INIT(empty0 + s * 8, 1);
        }
        MBARRIER_INIT(doneb, 1);
    }
    if ((tid >> 5) == 0) {
        TCGEN05_ALLOC(smem_u32(&tmem_slot), 256);
        TCGEN05_RELINQUISH();
    }
    __syncthreads();

    uint32_t tmem_base;
    asm volatile("ld.shared.b32 %0, [%1];" : "=r"(tmem_base)
                 : "r"(smem_u32(&tmem_slot)));

    // Hoisted k-invariant producer addressing
    uint32_t offA[4];
    const __half* aPtr[4];
#pragma unroll
    for (int i = 0; i < 4; i++) {
        int c = tid + i * 256;
        int row = c >> 3;
        int ci = c & 7;
        offA[i] = SWZ128((uint32_t)(row * 128 + ci * 16));
        aPtr[i] = Ag + (size_t)(m0 + row) * U2_ + ci * 8;
    }

    int prod_ph = 1, cons_ph = 0;

    for (int it = 0; it < KT + NST - 1; ++it) {
        if (it < KT) {
            const int s = it % NST;
            MBARRIER_WAIT_PARITY(empty0 + s * 8, prod_ph);
            const uint32_t aS = tb + s * STAGE_BYTES;
            const uint32_t bS = aS + 16384;
            const int kbase = it * 64;
            if (tid == 0) {
                MBARRIER_EXPECT_TX(full0 + s * 8, 32768u);
                TMA_2D(bS, tmw1, kbase, n0, full0 + s * 8);
            }
#pragma unroll
            for (int i = 0; i < 4; i++)
                cp_async16(aS + offA[i], aPtr[i] + kbase);
            cp_async_arrive_noinc(full0 + s * 8);
            if (s == NST - 1) prod_ph ^= 1;
        }
        const int ck = it - (NST - 1);
        if (ck >= 0 && tid == 0) {
            const int s = ck % NST;
            MBARRIER_WAIT_PARITY(full0 + s * 8, cons_ph);
            FENCE_PROXY_ASYNC();
            const uint32_t aS = tb + s * STAGE_BYTES;
            const uint32_t bS = aS + 16384;
            uint64_t ad = MAKE_SMEM_DESC(aS);
            uint64_t bd = MAKE_SMEM_DESC(bS);
#pragma unroll
            for (int ks = 0; ks < 4; ks++) {
                uint32_t en = (ck > 0 || ks > 0) ? 1u : 0u;
                mma_f16_ss(tmem_base, ad + 2 * ks, bd + 2 * ks, IDESC_F16, en);
            }
            TCGEN05_COMMIT(empty0 + s * 8);
            if (s == NST - 1) cons_ph ^= 1;
        }
    }
    if (tid == 0) TCGEN05_COMMIT(doneb);

    MBARRIER_WAIT_PARITY(doneb, 0);
    TCGEN05_FENCE_AFTER();

    const int w = tid >> 5, lane = tid & 31;
    const int half = w >> 2, sub = w & 3;
    const int mrow = m0 + sub * 32 + lane;
    __half* crow = Cg + (size_t)mrow * LDC + n0 + half * 128;

#pragma unroll
    for (int ch = 0; ch < 4; ch++) {
        uint32_t rr[32];
        TCGEN05_LD_X32(rr, tmem_base + half * 128 + ch * 32);
        TCGEN05_WAIT_LD();
        uint32_t hp[16];
#pragma unroll
        for (int j = 0; j < 16; j++) {
            float f0 = fmaxf(__uint_as_float(rr[2 * j]), 0.f);
            float f1 = fmaxf(__uint_as_float(rr[2 * j + 1]), 0.f);
            __half2 h = __floats2half2_rn(f0, f1);
            hp[j] = *reinterpret_cast<uint32_t*>(&h);
        }
#pragma unroll
        for (int q = 0; q < 4; q++) {
            uint4 v = make_uint4(hp[4 * q], hp[4 * q + 1],
                                 hp[4 * q + 2], hp[4 * q + 3]);
            *reinterpret_cast<uint4*>(crow + ch * 32 + q * 8) = v;
        }
    }

    __syncthreads();
    if ((tid >> 5) == 0) {
        TCGEN05_DEALLOC(tmem_base, 256);
    }
#endif
}

// ===========================================================================
// Fused stage B + C (hoisted offsets + fp16 x in epilogue):
//   tile u=128 x t=256, 2 CTAs/SM. A = WS2 (TMA 3D box 64x128);
//   B = hbar (cp.async). Register softmax + xh-weighted sum -> m.
// ===========================================================================
__global__ __launch_bounds__(256, 2)
void gemm_bc(const void* __restrict__ tmaps, const __half* __restrict__ hbar,
             const __half* __restrict__ xh, float* __restrict__ mout)
{
#if TCG_OK
    constexpr int KT  = 8;
    constexpr int LDH = R_ * DA_;
    const void* tmw2 = (const unsigned char*)tmaps + 128;

    extern __shared__ char dyn_smem[];
    __shared__ uint64_t bars[2 * NST + 1];
    __shared__ uint32_t tmem_slot;
    __shared__ float sMx[128], sZ[128], sW[128];

    const int tid = threadIdx.x;
    const int n0 = blockIdx.x * 128;   // u chunk
    const int b  = blockIdx.y;
    const int z  = blockIdx.z;         // r
    const int t0 = b * T_;

    const uint32_t raw = smem_u32(dyn_smem);
    const uint32_t tb = (raw + 1023u) & ~1023u;
    const uint32_t bar_base = smem_u32(&bars[0]);
    const uint32_t full0  = bar_base;
    const uint32_t empty0 = bar_base + NST * 8;
    const uint32_t doneb  = bar_base + 2 * NST * 8;

    if (tid == 0) {
#pragma unroll
        for (int s = 0; s < NST; s++) {
            MBARRIER_INIT(full0 + s * 8, FULL_CNT);
            MBARRIER_INIT(empty0 + s * 8, 1);
        }
        MBARRIER_INIT(doneb, 1);
    }
    if ((tid >> 5) == 0) {
        TCGEN05_ALLOC(smem_u32(&tmem_slot), 256);
        TCGEN05_RELINQUISH();
    }
    __syncthreads();

    uint32_t tmem_base;
    asm volatile("ld.shared.b32 %0, [%1];" : "=r"(tmem_base)
                 : "r"(smem_u32(&tmem_slot)));

    // Hoisted k-invariant producer addressing (hbar rows)
    uint32_t offB[8];
    const __half* bPtr[8];
#pragma unroll
    for (int i = 0; i < 8; i++) {
        int c = tid + i * 256;
        int row = c >> 3;
        int ci = c & 7;
        offB[i] = SWZ128((uint32_t)(row * 128 + ci * 16));
        bPtr[i] = hbar + (size_t)(t0 + row) * LDH + z * DA_ + ci * 8;
    }

    int prod_ph = 1, cons_ph = 0;

    for (int it = 0; it < KT + NST - 1; ++it) {
        if (it < KT) {
            const int s = it % NST;
            MBARRIER_WAIT_PARITY(empty0 + s * 8, prod_ph);
            const uint32_t aS = tb + s * STAGE_BYTES;
            const uint32_t bS = aS + 16384;
            const int kbase = it * 64;
            if (tid == 0) {
                MBARRIER_EXPECT_TX(full0 + s * 8, 16384u);
                TMA_3D(aS, tmw2, kbase, n0, z, full0 + s * 8);
            }
#pragma unroll
            for (int i = 0; i < 8; i++)
                cp_async16(bS + offB[i], bPtr[i] + kbase);
            cp_async_arrive_noinc(full0 + s * 8);
            if (s == NST - 1) prod_ph ^= 1;
        }
        const int ck = it - (NST - 1);
        if (ck >= 0 && tid == 0) {
            const int s = ck % NST;
            MBARRIER_WAIT_PARITY(full0 + s * 8, cons_ph);
            FENCE_PROXY_ASYNC();
            const uint32_t aS = tb + s * STAGE_BYTES;
            const uint32_t bS = aS + 16384;
            uint64_t ad = MAKE_SMEM_DESC(aS);
            uint64_t bd = MAKE_SMEM_DESC(bS);
#pragma unroll
            for (int ks = 0; ks < 4; ks++) {
                uint32_t en = (ck > 0 || ks > 0) ? 1u : 0u;
                mma_f16_ss(tmem_base, ad + 2 * ks, bd + 2 * ks, IDESC_F16, en);
            }
            TCGEN05_COMMIT(empty0 + s * 8);
            if (s == NST - 1) cons_ph ^= 1;
        }
    }
    if (tid == 0) TCGEN05_COMMIT(doneb);

    MBARRIER_WAIT_PARITY(doneb, 0);
    TCGEN05_FENCE_AFTER();

    // ---- register softmax-weighted-sum epilogue (two t-halves merged) -----
    const int w = tid >> 5, lane = tid & 31;
    const int half = w >> 2, sub = w & 3;
    const int urow = sub * 32 + lane;          // 0..127
    const int ug   = n0 + urow;
    const int tbase = half * 128;

    const __half* xp = xh + ((size_t)b * T_ + tbase) * U2_ + ug;  // stride U2_

    float mx = -3.4e38f, Z = 0.f, W = 0.f;
#pragma unroll
    for (int ch = 0; ch < 4; ch++) {
        uint32_t rr[32];
        TCGEN05_LD_X32(rr, tmem_base + tbase + ch * 32);
        TCGEN05_WAIT_LD();

        float s[32];
        float cmx = -3.4e38f;
#pragma unroll
        for (int j = 0; j < 32; j++) {
            s[j] = __uint_as_float(rr[j]);
            cmx = fmaxf(cmx, s[j]);
        }
        float nm = fmaxf(mx, cmx);
        float resc = __expf(mx - nm);
        Z *= resc;
        W *= resc;
#pragma unroll
        for (int j = 0; j < 32; j++) {
            float e = __expf(s[j] - nm);
            Z += e;
            W = fmaf(e, __half2float(xp[(size_t)(ch * 32 + j) * U2_]), W);
        }
        mx = nm;
    }

    // merge the two halves (threads tid and tid+128 share the same urow)
    if (half == 1) {
        sMx[urow] = mx; sZ[urow] = Z; sW[urow] = W;
    }
    __syncthreads();
    if (half == 0) {
        float mx2 = sMx[urow], Z2 = sZ[urow], W2 = sW[urow];
        float nm = fmaxf(mx, mx2);
        float e1 = __expf(mx - nm);
        float e2 = __expf(mx2 - nm);
        float Zt = Z * e1 + Z2 * e2;
        float Wt = W * e1 + W2 * e2;
        mout[((size_t)b * R_ + z) * U2_ + ug] = Wt / Zt;
    }

    __syncthreads();
    if ((tid >> 5) == 0) {
        TCGEN05_DEALLOC(tmem_base, 256);
    }
#endif
}

// ===========================================================================
// Stage D (split-K): votes partial = m_r[:, kh*512:(kh+1)*512] @ CW_r slice.
// grid (32, 2, 8): n0 = bx*64, kh = by, z = bz. Output to partial buffer kh.
// ===========================================================================
__global__ __launch_bounds__(256)
void sgemm_d(const float* __restrict__ Ag, const float* __restrict__ Bg,
             float* __restrict__ Cg)
{
    const int n0 = blockIdx.x * 64;
    const int kh = blockIdx.y;           // k half
    const int z  = blockIdx.z;
    const int kbeg = kh * 512;

    __shared__ float As[32][128 + 4];
    __shared__ float Bs[32][64 + 4];

    const int tid = threadIdx.x;
    const int tx = tid & 15;
    const int ty = tid >> 4;

    float acc[8][4];
#pragma unroll
    for (int i = 0; i < 8; i++)
#pragma unroll
        for (int j = 0; j < 4; j++) acc[i][j] = 0.f;

    for (int k0 = kbeg; k0 < kbeg + 512; k0 += 32) {
#pragma unroll
        for (int i = 0; i < 4; i++) {
            int f = tid + i * 256;
            int row = f >> 3;
            int kk = (f & 7) << 2;
            float4 v = *reinterpret_cast<const float4*>(
                Ag + (size_t)row * (R_ * U2_) + z * U2_ + k0 + kk);
            As[kk + 0][row] = v.x;
            As[kk + 1][row] = v.y;
            As[kk + 2][row] = v.z;
            As[kk + 3][row] = v.w;
        }
#pragma unroll
        for (int i = 0; i < 2; i++) {
            int f = tid + i * 256;
            int kr = f >> 4;
            int nn = (f & 15) << 2;
            float4 v = *reinterpret_cast<const float4*>(
                Bg + ((size_t)z * U2_ + k0 + kr) * (SC_ * OA_) + n0 + nn);
            *reinterpret_cast<float4*>(&Bs[kr][nn]) = v;
        }
        __syncthreads();

#pragma unroll
        for (int k = 0; k < 32; k++) {
            float a[8], bb[4];
            *reinterpret_cast<float4*>(&a[0]) =
                *reinterpret_cast<const float4*>(&As[k][ty * 8]);
            *reinterpret_cast<float4*>(&a[4]) =
                *reinterpret_cast<const float4*>(&As[k][ty * 8 + 4]);
            *reinterpret_cast<float4*>(&bb[0]) =
                *reinterpret_cast<const float4*>(&Bs[k][tx * 4]);
#pragma unroll
            for (int i = 0; i < 8; i++)
#pragma unroll
                for (int j = 0; j < 4; j++)
                    acc[i][j] = fmaf(a[i], bb[j], acc[i][j]);
        }
        __syncthreads();
    }

    float* out = Cg + (size_t)kh * B_ * R_ * SC_ * OA_;
#pragma unroll
    for (int i = 0; i < 8; i++) {
        size_t row = ty * 8 + i;
        float4 v = make_float4(acc[i][0], acc[i][1], acc[i][2], acc[i][3]);
        *reinterpret_cast<float4*>(
            out + row * (R_ * SC_ * OA_) + z * (SC_ * OA_) + n0 + tx * 4) = v;
    }
}

// ===========================================================================
// Stage E: dynamic routing (reads the two split-K vote partials).
// ===========================================================================
__global__ __launch_bounds__(256)
void routing_kernel(const float* __restrict__ votes, float* __restrict__ out)
{
    const int b = blockIdx.x;
    const int tid = threadIdx.x;
    const size_t vstride = (size_t)B_ * R_ * SC_ * OA_;
    const float* vb  = votes + (size_t)b * R_ * SC_ * OA_;
    const float* vb2 = vb + vstride;

    __shared__ float logits[R_][SC_];
    __shared__ float route[R_][SC_];
    __shared__ float act[SC_ * OA_];
    __shared__ float fac[SC_];

    for (int i = tid; i < R_ * SC_; i += 256)
        (&logits[0][0])[i] = 0.f;
    __syncthreads();

    for (int it = 0; it < NR_; it++) {
        int w = tid >> 5, lane = tid & 31;
        if (w < R_) {
            float v0 = logits[w][lane];
            float v1 = logits[w][lane + 32];
            float v2 = logits[w][lane + 64];
            float v3 = logits[w][lane + 96];
            float mx = fmaxf(fmaxf(v0, v1), fmaxf(v2, v3));
#pragma unroll
            for (int off = 16; off; off >>= 1)
                mx = fmaxf(mx, __shfl_xor_sync(0xFFFFFFFFu, mx, off));
            float e0 = expf(v0 - mx), e1 = expf(v1 - mx);
            float e2 = expf(v2 - mx), e3 = expf(v3 - mx);
            float s = e0 + e1 + e2 + e3;
#pragma unroll
            for (int off = 16; off; off >>= 1)
                s += __shfl_xor_sync(0xFFFFFFFFu, s, off);
            float inv = 1.f / s;
            route[w][lane]      = e0 * inv;
            route[w][lane + 32] = e1 * inv;
            route[w][lane + 64] = e2 * inv;
            route[w][lane + 96] = e3 * inv;
        }
        __syncthreads();

        for (int idx = tid; idx < SC_ * OA_; idx += 256) {
            int c = idx >> 4, o = idx & 15;
            float s = 0.f;
#pragma unroll
            for (int r = 0; r < R_; r++) {
                size_t vi = ((size_t)r * SC_ + c) * OA_ + o;
                s = fmaf(route[r][c], vb[vi] + vb2[vi], s);
            }
            act[idx] = s;
        }
        __syncthreads();

        if (tid < SC_) {
            float n2 = 0.f;
#pragma unroll
            for (int o = 0; o < OA_; o++) {
                float v = act[tid * OA_ + o];
                n2 = fmaf(v, v, n2);
            }
            fac[tid] = sqrtf(n2) / (1.f + n2);
        }
        __syncthreads();
        for (int idx = tid; idx < SC_ * OA_; idx += 256)
            act[idx] *= fac[idx >> 4];
        __syncthreads();

        if (it < NR_ - 1) {
            for (int idx = tid; idx < R_ * SC_; idx += 256) {
                int r = idx >> 7, c = idx & 127;
                float d = 0.f;
#pragma unroll
                for (int o = 0; o < OA_; o++) {
                    size_t vi = ((size_t)r * SC_ + c) * OA_ + o;
                    d = fmaf(vb[vi] + vb2[vi], act[c * OA_ + o], d);
                }
                logits[r][c] += d;
            }
            __syncthreads();
        }
    }

    if (tid < SC_) {
        float n2 = 0.f;
#pragma unroll
        for (int o = 0; o < OA_; o++) {
            float v = act[tid * OA_ + o];
            n2 = fmaf(v, v, n2);
        }
        out[(long)b * SC_ + tid] = sqrtf(n2);
    }
}

// ===========================================================================
// Host: tensor-map construction (driver entry point; no -lcuda link needed)
// ===========================================================================
typedef CUresult (CUDAAPI *PFN_encodeTiled)(
    CUtensorMap*, CUtensorMapDataType, cuuint32_t, void*,
    const cuuint64_t*, const cuuint64_t*, const cuuint32_t*, const cuuint32_t*,
    CUtensorMapInterleave, CUtensorMapSwizzle, CUtensorMapL2promotion,
    CUtensorMapFloatOOBfill);

extern "C" void kernel_launch(void* const* d_in, const int* in_sizes, int n_in,
                              void* d_out, int out_size)
{
    const float* x   = (const float*)d_in[0];  // [B,T,U2]
    const float* WS1 = (const float*)d_in[1];  // [R,DA,U2]
    const float* WS2 = (const float*)d_in[2];  // [R,U2,DA]
    const float* CW  = (const float*)d_in[3];  // [R,U2,SC*OA]
    float* out = (float*)d_out;                // [B,SC]

    __half *xh, *w1h, *w2h, *hbar;
    float *m, *votes;
    unsigned char* dtm;
    cudaGetSymbolAddress((void**)&xh,    g_xh);
    cudaGetSymbolAddress((void**)&w1h,   g_w1h);
    cudaGetSymbolAddress((void**)&w2h,   g_w2h);
    cudaGetSymbolAddress((void**)&hbar,  g_hbar);
    cudaGetSymbolAddress((void**)&m,     g_m);
    cudaGetSymbolAddress((void**)&votes, g_votes);
    cudaGetSymbolAddress((void**)&dtm,   g_tmaps);

    // Tensor maps (deterministic; same every call).
    PFN_encodeTiled enc = nullptr;
    cudaDriverEntryPointQueryResult qr;
    cudaGetDriverEntryPoint("cuTensorMapEncodeTiled", (void**)&enc,
                            cudaEnableDefault, &qr);
    static CUtensorMap h_tm[2];
    // [0] WS1 fp16: 2D [U2 cols, R*DA rows], box 64x256, SW128
    {
        cuuint64_t dims[2] = {U2_, (uint64_t)R_ * DA_};
        cuuint64_t strides[1] = {(uint64_t)U2_ * 2};
        cuuint32_t box[2] = {64, 256};
        cuuint32_t es[2] = {1, 1};
        enc(&h_tm[0], CU_TENSOR_MAP_DATA_TYPE_FLOAT16, 2, (void*)w1h,
            dims, strides, box, es,
            CU_TENSOR_MAP_INTERLEAVE_NONE, CU_TENSOR_MAP_SWIZZLE_128B,
            CU_TENSOR_MAP_L2_PROMOTION_L2_128B,
            CU_TENSOR_MAP_FLOAT_OOB_FILL_NONE);
    }
    // [1] WS2 fp16: 3D [DA cols, U2 rows, R planes], box 64x128x1, SW128
    {
        cuuint64_t dims[3] = {DA_, U2_, R_};
        cuuint64_t strides[2] = {(uint64_t)DA_ * 2, (uint64_t)U2_ * DA_ * 2};
        cuuint32_t box[3] = {64, 128, 1};
        cuuint32_t es[3] = {1, 1, 1};
        enc(&h_tm[1], CU_TENSOR_MAP_DATA_TYPE_FLOAT16, 3, (void*)w2h,
            dims, strides, box, es,
            CU_TENSOR_MAP_INTERLEAVE_NONE, CU_TENSOR_MAP_SWIZZLE_128B,
            CU_TENSOR_MAP_L2_PROMOTION_L2_128B,
            CU_TENSOR_MAP_FLOAT_OOB_FILL_NONE);
    }
    cudaMemcpyAsync(dtm, h_tm, sizeof(h_tm), cudaMemcpyHostToDevice, 0);

    cudaFuncSetAttribute(gemm_a,
                         cudaFuncAttributeMaxDynamicSharedMemorySize, GEMM_DSMEM);
    cudaFuncSetAttribute(gemm_bc,
                         cudaFuncAttributeMaxDynamicSharedMemorySize, GEMM_DSMEM);

    // Convert inputs to fp16
    {
        long nx = (long)B_ * T_ * U2_;
        long n1 = (long)R_ * DA_ * U2_;
        long n2 = (long)R_ * U2_ * DA_;
        f2h_kernel<<<(unsigned)((nx / 8 + 255) / 256), 256>>>(x, xh, nx);
        f2h_kernel<<<(unsigned)((n1 / 8 + 255) / 256), 256>>>(WS1, w1h, n1);
        f2h_kernel<<<(unsigned)((n2 / 8 + 255) / 256), 256>>>(WS2, w2h, n2);
    }

    // Stage A: hbar = relu(x @ WS1^T)  (f16; tile 128x256, 2 CTAs/SM)
    {
        dim3 grid((R_ * DA_) / 256, (B_ * T_) / 128, 1);   // (16, 256)
        gemm_a<<<grid, 256, GEMM_DSMEM>>>(dtm, xh, hbar);
    }

    // Fused B+C: tile u=128 x t=256, 2 CTAs/SM; fp16 x in epilogue.
    {
        dim3 grid(U2_ / 128, B_, R_);                      // (8, 128, 8)
        gemm_bc<<<grid, 256, GEMM_DSMEM>>>(dtm, hbar, xh, m);
    }

    // Stage D: split-K votes partials (fp32), grid (32, 2, 8)
    {
        dim3 grid((SC_ * OA_) / 64, 2, R_);
        sgemm_d<<<grid, 256>>>(m, CW, votes);
    }

    // Stage E: dynamic routing + final class logits
    routing_kernel<<<B_, 256>>>(votes, out);
}

// round 17
// speedup vs baseline: 1.1442x; 1.0128x over previous
#include <cuda.h>
#include <cuda_runtime.h>
#include <cuda_bf16.h>
#include <cuda_fp16.h>
#include <math.h>
#include <stdint.h>

// Problem constants
#define B_  128
#define T_  256
#define U2_ 1024
#define DA_ 512
#define R_  8
#define SC_ 128
#define OA_ 16
#define NR_ 3

// tcgen05 only exists in the arch-specific (sm_103a) compilation pass.
#if !defined(__CUDA_ARCH__) || defined(__CUDA_ARCH_FEAT_SM103_ALL)
#define TCG_OK 1
#else
#define TCG_OK 0
#endif

// Scratch in __device__ globals (allocation-free rule)
__device__ __half g_xh[(long)B_ * T_ * U2_];          // x fp16
__device__ __half g_w1h[(long)R_ * DA_ * U2_];        // WS1 fp16
__device__ __half g_w2h[(long)R_ * U2_ * DA_];        // WS2 fp16
__device__ __half g_hbar[(long)B_ * T_ * R_ * DA_];   // hbar fp16 [bt, r*DA+a]
__device__ float  g_m[(long)B_ * R_ * U2_];           // [b, r*U2+u]
__device__ float  g_votes[2L * B_ * R_ * SC_ * OA_];  // split-K partials
// Tensor maps: [0]=WS1(fp16,2D), [1]=WS2(fp16,3D)
__device__ __align__(128) unsigned char g_tmaps[2 * 128];

// ===========================================================================
// PTX helpers
// ===========================================================================
__device__ __forceinline__ uint32_t smem_u32(const void* p) {
    uint32_t a;
    asm("{ .reg .u64 t; cvta.to.shared.u64 t, %1; cvt.u32.u64 %0, t; }"
        : "=r"(a) : "l"(p));
    return a;
}

#define MBARRIER_INIT(addr, count) \
    asm volatile("mbarrier.init.shared.b64 [%0], %1;" \
                 :: "r"((uint32_t)(addr)), "r"((uint32_t)(count)) : "memory")

#define MBARRIER_EXPECT_TX(addr, bytes) \
    asm volatile("mbarrier.arrive.expect_tx.shared.b64 _, [%0], %1;" \
                 :: "r"((uint32_t)(addr)), "r"((uint32_t)(bytes)) : "memory")

#define MBARRIER_WAIT_PARITY(mbar_smem_addr, phase_parity) do { \
    uint32_t _mbar = (uint32_t)(mbar_smem_addr); \
    uint32_t _parity = (uint32_t)(phase_parity); \
    uint32_t _done; \
    asm volatile( \
        "{\n\t" \
        ".reg .pred p;\n\t" \
        "mbarrier.try_wait.parity.acquire.cta.shared::cta.b64 p, [%1], %2;\n\t" \
        "selp.b32 %0, 1, 0, p;\n\t" \
        "}" \
        : "=r"(_done) : "r"(_mbar), "r"(_parity) : "memory"); \
    if (!_done) { \
        asm volatile( \
            "{\n\t" \
            ".reg .pred P1;\n\t" \
            "WAIT_LOOP_%=:\n\t" \
            "mbarrier.try_wait.parity.acquire.cta.shared::cta.b64 P1, [%0], %1, 0x989680;\n\t" \
            "@P1 bra.uni WAIT_DONE_%=;\n\t" \
            "bra.uni WAIT_LOOP_%=;\n\t" \
            "WAIT_DONE_%=:\n\t" \
            "}" \
            :: "r"(_mbar), "r"(_parity) : "memory"); \
    } \
} while(0)

#if TCG_OK
#define TCGEN05_ALLOC(smem_result_addr, nCols) \
    asm volatile("tcgen05.alloc.cta_group::1.sync.aligned.shared::cta.b32 [%0], %1;" \
                 :: "r"((uint32_t)(smem_result_addr)), "r"((uint32_t)(nCols)) : "memory")
#define TCGEN05_DEALLOC(tmem_addr, nCols) \
    asm volatile("tcgen05.dealloc.cta_group::1.sync.aligned.b32 %0, %1;" \
                 :: "r"(tmem_addr), "r"((uint32_t)(nCols)))
#define TCGEN05_RELINQUISH() \
    asm volatile("tcgen05.relinquish_alloc_permit.cta_group::1.sync.aligned;")
#define TCGEN05_COMMIT(mbar) \
    asm volatile("tcgen05.commit.cta_group::1.mbarrier::arrive::one.shared::cluster.b64 [%0];" \
                 :: "r"((uint32_t)(mbar)) : "memory")
#define TCGEN05_WAIT_LD() \
    asm volatile("tcgen05.wait::ld.sync.aligned;" ::: "memory")
#define TCGEN05_FENCE_AFTER() \
    asm volatile("tcgen05.fence::after_thread_sync;" ::: "memory")
#define FENCE_PROXY_ASYNC() \
    asm volatile("fence.proxy.async.shared::cta;" ::: "memory")

#define TMA_2D(smem, tmap, cx, cy, mbar) \
    asm volatile("cp.async.bulk.tensor.2d.shared::cta.global.tile.mbarrier::complete_tx::bytes " \
                 "[%0], [%1, {%2, %3}], [%4];" \
                 :: "r"((uint32_t)(smem)), "l"(tmap), "r"((int)(cx)), "r"((int)(cy)), \
                    "r"((uint32_t)(mbar)) : "memory")
#define TMA_3D(smem, tmap, cx, cy, cz, mbar) \
    asm volatile("cp.async.bulk.tensor.3d.shared::cta.global.tile.mbarrier::complete_tx::bytes " \
                 "[%0], [%1, {%2, %3, %4}], [%5];" \
                 :: "r"((uint32_t)(smem)), "l"(tmap), "r"((int)(cx)), "r"((int)(cy)), \
                    "r"((int)(cz)), "r"((uint32_t)(mbar)) : "memory")

#define TCGEN05_LD_X32(r, tmem_addr) \
    asm volatile( \
        "tcgen05.ld.sync.aligned.32x32b.x32.b32 " \
        "{%0, %1, %2, %3, %4, %5, %6, %7, " \
        " %8, %9, %10, %11, %12, %13, %14, %15, " \
        " %16, %17, %18, %19, %20, %21, %22, %23, " \
        " %24, %25, %26, %27, %28, %29, %30, %31}, [%32];" \
        : "=r"((r)[0]),  "=r"((r)[1]),  "=r"((r)[2]),  "=r"((r)[3]), \
          "=r"((r)[4]),  "=r"((r)[5]),  "=r"((r)[6]),  "=r"((r)[7]), \
          "=r"((r)[8]),  "=r"((r)[9]),  "=r"((r)[10]), "=r"((r)[11]), \
          "=r"((r)[12]), "=r"((r)[13]), "=r"((r)[14]), "=r"((r)[15]), \
          "=r"((r)[16]), "=r"((r)[17]), "=r"((r)[18]), "=r"((r)[19]), \
          "=r"((r)[20]), "=r"((r)[21]), "=r"((r)[22]), "=r"((r)[23]), \
          "=r"((r)[24]), "=r"((r)[25]), "=r"((r)[26]), "=r"((r)[27]), \
          "=r"((r)[28]), "=r"((r)[29]), "=r"((r)[30]), "=r"((r)[31]) \
        : "r"(tmem_addr))

// f16 SS MMA, cta_group::1, fp32 accumulate
__device__ __forceinline__ void mma_f16_ss(uint32_t d_tmem, uint64_t a_desc,
                                           uint64_t b_desc, uint32_t idesc,
                                           uint32_t enable) {
    asm volatile(
        "{\n\t"
        ".reg .pred p;\n\t"
        "setp.ne.u32 p, %4, 0;\n\t"
        "tcgen05.mma.cta_group::1.kind::f16 [%0], %1, %2, %3, p;\n\t"
        "}"
        :: "r"(d_tmem), "l"(a_desc), "l"(b_desc), "r"(idesc), "r"(enable)
        : "memory");
}
#endif // TCG_OK

// SW128 K-major smem descriptor (version=1 Blackwell, LBO=1, SBO=64)
static constexpr uint64_t SMEM_DESC_BASE_SW128 =
    (uint64_t(2)  << 61) | (uint64_t(1) << 46) |
    (uint64_t(64) << 32) | (uint64_t(1) << 16);
#define MAKE_SMEM_DESC(base_addr) \
    (SMEM_DESC_BASE_SW128 | ((uint64_t)((base_addr) >> 4) & 0x3FFF))
#define SWZ128(off) ((off) ^ (((off) >> 3) & 0x70))

__device__ __forceinline__ void cp_async16(uint32_t dst, const void* src) {
    asm volatile("cp.async.cg.shared.global [%0], [%1], 16;"
                 :: "r"(dst), "l"(src) : "memory");
}
__device__ __forceinline__ void cp_async_arrive_noinc(uint32_t mbar) {
    asm volatile("cp.async.mbarrier.arrive.noinc.shared::cta.b64 [%0];"
                 :: "r"(mbar) : "memory");
}

// ===========================================================================
// Pipeline config: tile M=128 x N=256, stage 48KB (A 16KB + B 32KB), NST=2,
// 2 CTAs/SM. full arrivals: 256 cp.async + 1 expect_tx = 257.
// ===========================================================================
#define NST 2
#define STAGE_BYTES 49152
#define GEMM_DSMEM (1024 + NST * STAGE_BYTES)
#define FULL_CNT 257

// idesc f16: c=F32(1<<4), fp16 A/B, N=256 (32<<17), M=128 (8<<24)
static constexpr uint32_t IDESC_F16 =
    (1u << 4) | (32u << 17) | (8u << 24);

// ===========================================================================
// Fused fp32 -> fp16 conversion over three segments (x | WS1 | WS2) in one
// launch. Segment bounds are compile-time; branchless-ish decode.
// ===========================================================================
#define NX_ ((long)B_ * T_ * U2_)               // 33554432
#define N1_ ((long)R_ * DA_ * U2_)              //  4194304
#define N2_ ((long)R_ * U2_ * DA_)              //  4194304
#define NTOT_ (NX_ + N1_ + N2_)

__global__ __launch_bounds__(256)
void f2h_all_kernel(const float* __restrict__ x, const float* __restrict__ w1,
                    const float* __restrict__ w2, __half* __restrict__ xh,
                    __half* __restrict__ w1h, __half* __restrict__ w2h)
{
    long i = ((long)blockIdx.x * blockDim.x + threadIdx.x) * 8;
    if (i >= NTOT_) return;

    const float* src;
    __half* dst;
    long off;
    if (i < NX_)            { src = x;  dst = xh;  off = i; }
    else if (i < NX_ + N1_) { src = w1; dst = w1h; off = i - NX_; }
    else                    { src = w2; dst = w2h; off = i - NX_ - N1_; }

    float4 a = *reinterpret_cast<const float4*>(src + off);
    float4 b = *reinterpret_cast<const float4*>(src + off + 4);
    __half2 h0 = __floats2half2_rn(a.x, a.y);
    __half2 h1 = __floats2half2_rn(a.z, a.w);
    __half2 h2 = __floats2half2_rn(b.x, b.y);
    __half2 h3 = __floats2half2_rn(b.z, b.w);
    uint4 v;
    v.x = *reinterpret_cast<uint32_t*>(&h0);
    v.y = *reinterpret_cast<uint32_t*>(&h1);
    v.z = *reinterpret_cast<uint32_t*>(&h2);
    v.w = *reinterpret_cast<uint32_t*>(&h3);
    *reinterpret_cast<uint4*>(dst + off) = v;
}

// ===========================================================================
// Stage A: f16 GEMM, tile 128x256x64, 2 CTAs/SM (hoisted producer offsets).
// A = x (cp.async); B = WS1 (TMA box 64x256). hbar = relu(x @ WS1^T), fp16.
// ===========================================================================
__global__ __launch_bounds__(256, 2)
void gemm_a(const void* __restrict__ tmaps, const __half* __restrict__ Ag,
            __half* __restrict__ Cg)
{
#if TCG_OK
    constexpr int KT  = 16;
    constexpr int LDC = R_ * DA_;
    const void* tmw1 = (const unsigned char*)tmaps;

    extern __shared__ char dyn_smem[];
    __shared__ uint64_t bars[2 * NST + 1];
    __shared__ uint32_t tmem_slot;

    const int tid = threadIdx.x;
    const int n0 = blockIdx.x * 256;
    const int m0 = blockIdx.y * 128;

    const uint32_t raw = smem_u32(dyn_smem);
    const uint32_t tb = (raw + 1023u) & ~1023u;
    const uint32_t bar_base = smem_u32(&bars[0]);
    const uint32_t full0  = bar_base;
    const uint32_t empty0 = bar_base + NST * 8;
    const uint32_t doneb  = bar_base + 2 * NST * 8;

    if (tid == 0) {
#pragma unroll
        for (int s = 0; s < NST; s++) {
            MBARRIER_INIT(full0 + s * 8, FULL_CNT);
            MBARRIER_INIT(empty0 + s * 8, 1);
        }
        MBARRIER_INIT(doneb, 1);
    }
    if ((tid >> 5) == 0) {
        TCGEN05_ALLOC(smem_u32(&tmem_slot), 256);
        TCGEN05_RELINQUISH();
    }
    __syncthreads();

    uint32_t tmem_base;
    asm volatile("ld.shared.b32 %0, [%1];" : "=r"(tmem_base)
                 : "r"(smem_u32(&tmem_slot)));

    // Hoisted k-invariant producer addressing
    uint32_t offA[4];
    const __half* aPtr[4];
#pragma unroll
    for (int i = 0; i < 4; i++) {
        int c = tid + i * 256;
        int row = c >> 3;
        int ci = c & 7;
        offA[i] = SWZ128((uint32_t)(row * 128 + ci * 16));
        aPtr[i] = Ag + (size_t)(m0 + row) * U2_ + ci * 8;
    }

    int prod_ph = 1, cons_ph = 0;

    for (int it = 0; it < KT + NST - 1; ++it) {
        if (it < KT) {
            const int s = it % NST;
            MBARRIER_WAIT_PARITY(empty0 + s * 8, prod_ph);
            const uint32_t aS = tb + s * STAGE_BYTES;
            const uint32_t bS = aS + 16384;
            const int kbase = it * 64;
            if (tid == 0) {
                MBARRIER_EXPECT_TX(full0 + s * 8, 32768u);
                TMA_2D(bS, tmw1, kbase, n0, full0 + s * 8);
            }
#pragma unroll
            for (int i = 0; i < 4; i++)
                cp_async16(aS + offA[i], aPtr[i] + kbase);
            cp_async_arrive_noinc(full0 + s * 8);
            if (s == NST - 1) prod_ph ^= 1;
        }
        const int ck = it - (NST - 1);
        if (ck >= 0 && tid == 0) {
            const int s = ck % NST;
            MBARRIER_WAIT_PARITY(full0 + s * 8, cons_ph);
            FENCE_PROXY_ASYNC();
            const uint32_t aS = tb + s * STAGE_BYTES;
            const uint32_t bS = aS + 16384;
            uint64_t ad = MAKE_SMEM_DESC(aS);
            uint64_t bd = MAKE_SMEM_DESC(bS);
#pragma unroll
            for (int ks = 0; ks < 4; ks++) {
                uint32_t en = (ck > 0 || ks > 0) ? 1u : 0u;
                mma_f16_ss(tmem_base, ad + 2 * ks, bd + 2 * ks, IDESC_F16, en);
            }
            TCGEN05_COMMIT(empty0 + s * 8);
            if (s == NST - 1) cons_ph ^= 1;
        }
    }
    if (tid == 0) TCGEN05_COMMIT(doneb);

    MBARRIER_WAIT_PARITY(doneb, 0);
    TCGEN05_FENCE_AFTER();

    const int w = tid >> 5, lane = tid & 31;
    const int half = w >> 2, sub = w & 3;
    const int mrow = m0 + sub * 32 + lane;
    __half* crow = Cg + (size_t)mrow * LDC + n0 + half * 128;

#pragma unroll
    for (int ch = 0; ch < 4; ch++) {
        uint32_t rr[32];
        TCGEN05_LD_X32(rr, tmem_base + half * 128 + ch * 32);
        TCGEN05_WAIT_LD();
        uint32_t hp[16];
#pragma unroll
        for (int j = 0; j < 16; j++) {
            float f0 = fmaxf(__uint_as_float(rr[2 * j]), 0.f);
            float f1 = fmaxf(__uint_as_float(rr[2 * j + 1]), 0.f);
            __half2 h = __floats2half2_rn(f0, f1);
            hp[j] = *reinterpret_cast<uint32_t*>(&h);
        }
#pragma unroll
        for (int q = 0; q < 4; q++) {
            uint4 v = make_uint4(hp[4 * q], hp[4 * q + 1],
                                 hp[4 * q + 2], hp[4 * q + 3]);
            *reinterpret_cast<uint4*>(crow + ch * 32 + q * 8) = v;
        }
    }

    __syncthreads();
    if ((tid >> 5) == 0) {
        TCGEN05_DEALLOC(tmem_base, 256);
    }
#endif
}

// ===========================================================================
// Fused stage B + C (hoisted offsets + fp16 x in epilogue):
//   tile u=128 x t=256, 2 CTAs/SM. A = WS2 (TMA 3D box 64x128);
//   B = hbar (cp.async). Register softmax + xh-weighted sum -> m.
// ===========================================================================
__global__ __launch_bounds__(256, 2)
void gemm_bc(const void* __restrict__ tmaps, const __half* __restrict__ hbar,
             const __half* __restrict__ xh, float* __restrict__ mout)
{
#if TCG_OK
    constexpr int KT  = 8;
    constexpr int LDH = R_ * DA_;
    const void* tmw2 = (const unsigned char*)tmaps + 128;

    extern __shared__ char dyn_smem[];
    __shared__ uint64_t bars[2 * NST + 1];
    __shared__ uint32_t tmem_slot;
    __shared__ float sMx[128], sZ[128], sW[128];

    const int tid = threadIdx.x;
    const int n0 = blockIdx.x * 128;   // u chunk
    const int b  = blockIdx.y;
    const int z  = blockIdx.z;         // r
    const int t0 = b * T_;

    const uint32_t raw = smem_u32(dyn_smem);
    const uint32_t tb = (raw + 1023u) & ~1023u;
    const uint32_t bar_base = smem_u32(&bars[0]);
    const uint32_t full0  = bar_base;
    const uint32_t empty0 = bar_base + NST * 8;
    const uint32_t doneb  = bar_base + 2 * NST * 8;

    if (tid == 0) {
#pragma unroll
        for (int s = 0; s < NST; s++) {
            MBARRIER_INIT(full0 + s * 8, FULL_CNT);
            MBARRIER_INIT(empty0 + s * 8, 1);
        }
        MBARRIER_INIT(doneb, 1);
    }
    if ((tid >> 5) == 0) {
        TCGEN05_ALLOC(smem_u32(&tmem_slot), 256);
        TCGEN05_RELINQUISH();
    }
    __syncthreads();

    uint32_t tmem_base;
    asm volatile("ld.shared.b32 %0, [%1];" : "=r"(tmem_base)
                 : "r"(smem_u32(&tmem_slot)));

    // Hoisted k-invariant producer addressing (hbar rows)
    uint32_t offB[8];
    const __half* bPtr[8];
#pragma unroll
    for (int i = 0; i < 8; i++) {
        int c = tid + i * 256;
        int row = c >> 3;
        int ci = c & 7;
        offB[i] = SWZ128((uint32_t)(row * 128 + ci * 16));
        bPtr[i] = hbar + (size_t)(t0 + row) * LDH + z * DA_ + ci * 8;
    }

    int prod_ph = 1, cons_ph = 0;

    for (int it = 0; it < KT + NST - 1; ++it) {
        if (it < KT) {
            const int s = it % NST;
            MBARRIER_WAIT_PARITY(empty0 + s * 8, prod_ph);
            const uint32_t aS = tb + s * STAGE_BYTES;
            const uint32_t bS = aS + 16384;
            const int kbase = it * 64;
            if (tid == 0) {
                MBARRIER_EXPECT_TX(full0 + s * 8, 16384u);
                TMA_3D(aS, tmw2, kbase, n0, z, full0 + s * 8);
            }
#pragma unroll
            for (int i = 0; i < 8; i++)
                cp_async16(bS + offB[i], bPtr[i] + kbase);
            cp_async_arrive_noinc(full0 + s * 8);
            if (s == NST - 1) prod_ph ^= 1;
        }
        const int ck = it - (NST - 1);
        if (ck >= 0 && tid == 0) {
            const int s = ck % NST;
            MBARRIER_WAIT_PARITY(full0 + s * 8, cons_ph);
            FENCE_PROXY_ASYNC();
            const uint32_t aS = tb + s * STAGE_BYTES;
            const uint32_t bS = aS + 16384;
            uint64_t ad = MAKE_SMEM_DESC(aS);
            uint64_t bd = MAKE_SMEM_DESC(bS);
#pragma unroll
            for (int ks = 0; ks < 4; ks++) {
                uint32_t en = (ck > 0 || ks > 0) ? 1u : 0u;
                mma_f16_ss(tmem_base, ad + 2 * ks, bd + 2 * ks, IDESC_F16, en);
            }
            TCGEN05_COMMIT(empty0 + s * 8);
            if (s == NST - 1) cons_ph ^= 1;
        }
    }
    if (tid == 0) TCGEN05_COMMIT(doneb);

    MBARRIER_WAIT_PARITY(doneb, 0);
    TCGEN05_FENCE_AFTER();

    // ---- register softmax-weighted-sum epilogue (two t-halves merged) -----
    const int w = tid >> 5, lane = tid & 31;
    const int half = w >> 2, sub = w & 3;
    const int urow = sub * 32 + lane;          // 0..127
    const int ug   = n0 + urow;
    const int tbase = half * 128;

    const __half* xp = xh + ((size_t)b * T_ + tbase) * U2_ + ug;  // stride U2_

    float mx = -3.4e38f, Z = 0.f, W = 0.f;
#pragma unroll
    for (int ch = 0; ch < 4; ch++) {
        uint32_t rr[32];
        TCGEN05_LD_X32(rr, tmem_base + tbase + ch * 32);
        TCGEN05_WAIT_LD();

        float s[32];
        float cmx = -3.4e38f;
#pragma unroll
        for (int j = 0; j < 32; j++) {
            s[j] = __uint_as_float(rr[j]);
            cmx = fmaxf(cmx, s[j]);
        }
        float nm = fmaxf(mx, cmx);
        float resc = __expf(mx - nm);
        Z *= resc;
        W *= resc;
#pragma unroll
        for (int j = 0; j < 32; j++) {
            float e = __expf(s[j] - nm);
            Z += e;
            W = fmaf(e, __half2float(xp[(size_t)(ch * 32 + j) * U2_]), W);
        }
        mx = nm;
    }

    // merge the two halves (threads tid and tid+128 share the same urow)
    if (half == 1) {
        sMx[urow] = mx; sZ[urow] = Z; sW[urow] = W;
    }
    __syncthreads();
    if (half == 0) {
        float mx2 = sMx[urow], Z2 = sZ[urow], W2 = sW[urow];
        float nm = fmaxf(mx, mx2);
        float e1 = __expf(mx - nm);
        float e2 = __expf(mx2 - nm);
        float Zt = Z * e1 + Z2 * e2;
        float Wt = W * e1 + W2 * e2;
        mout[((size_t)b * R_ + z) * U2_ + ug] = Wt / Zt;
    }

    __syncthreads();
    if ((tid >> 5) == 0) {
        TCGEN05_DEALLOC(tmem_base, 256);
    }
#endif
}

// ===========================================================================
// Stage D (split-K): votes partial = m_r[:, kh*512:(kh+1)*512] @ CW_r slice.
// grid (32, 2, 8): n0 = bx*64, kh = by, z = bz. Output to partial buffer kh.
// ===========================================================================
__global__ __launch_bounds__(256)
void sgemm_d(const float* __restrict__ Ag, const float* __restrict__ Bg,
             float* __restrict__ Cg)
{
    const int n0 = blockIdx.x * 64;
    const int kh = blockIdx.y;           // k half
    const int z  = blockIdx.z;
    const int kbeg = kh * 512;

    __shared__ float As[32][128 + 4];
    __shared__ float Bs[32][64 + 4];

    const int tid = threadIdx.x;
    const int tx = tid & 15;
    const int ty = tid >> 4;

    float acc[8][4];
#pragma unroll
    for (int i = 0; i < 8; i++)
#pragma unroll
        for (int j = 0; j < 4; j++) acc[i][j] = 0.f;

    for (int k0 = kbeg; k0 < kbeg + 512; k0 += 32) {
#pragma unroll
        for (int i = 0; i < 4; i++) {
            int f = tid + i * 256;
            int row = f >> 3;
            int kk = (f & 7) << 2;
            float4 v = *reinterpret_cast<const float4*>(
                Ag + (size_t)row * (R_ * U2_) + z * U2_ + k0 + kk);
            As[kk + 0][row] = v.x;
            As[kk + 1][row] = v.y;
            As[kk + 2][row] = v.z;
            As[kk + 3][row] = v.w;
        }
#pragma unroll
        for (int i = 0; i < 2; i++) {
            int f = tid + i * 256;
            int kr = f >> 4;
            int nn = (f & 15) << 2;
            float4 v = *reinterpret_cast<const float4*>(
                Bg + ((size_t)z * U2_ + k0 + kr) * (SC_ * OA_) + n0 + nn);
            *reinterpret_cast<float4*>(&Bs[kr][nn]) = v;
        }
        __syncthreads();

#pragma unroll
        for (int k = 0; k < 32; k++) {
            float a[8], bb[4];
            *reinterpret_cast<float4*>(&a[0]) =
                *reinterpret_cast<const float4*>(&As[k][ty * 8]);
            *reinterpret_cast<float4*>(&a[4]) =
                *reinterpret_cast<const float4*>(&As[k][ty * 8 + 4]);
            *reinterpret_cast<float4*>(&bb[0]) =
                *reinterpret_cast<const float4*>(&Bs[k][tx * 4]);
#pragma unroll
            for (int i = 0; i < 8; i++)
#pragma unroll
                for (int j = 0; j < 4; j++)
                    acc[i][j] = fmaf(a[i], bb[j], acc[i][j]);
        }
        __syncthreads();
    }

    float* out = Cg + (size_t)kh * B_ * R_ * SC_ * OA_;
#pragma unroll
    for (int i = 0; i < 8; i++) {
        size_t row = ty * 8 + i;
        float4 v = make_float4(acc[i][0], acc[i][1], acc[i][2], acc[i][3]);
        *reinterpret_cast<float4*>(
            out + row * (R_ * SC_ * OA_) + z * (SC_ * OA_) + n0 + tx * 4) = v;
    }
}

// ===========================================================================
// Stage E: dynamic routing (reads the two split-K vote partials).
// ===========================================================================
__global__ __launch_bounds__(256)
void routing_kernel(const float* __restrict__ votes, float* __restrict__ out)
{
    const int b = blockIdx.x;
    const int tid = threadIdx.x;
    const size_t vstride = (size_t)B_ * R_ * SC_ * OA_;
    const float* vb  = votes + (size_t)b * R_ * SC_ * OA_;
    const float* vb2 = vb + vstride;

    __shared__ float logits[R_][SC_];
    __shared__ float route[R_][SC_];
    __shared__ float act[SC_ * OA_];
    __shared__ float fac[SC_];

    for (int i = tid; i < R_ * SC_; i += 256)
        (&logits[0][0])[i] = 0.f;
    __syncthreads();

    for (int it = 0; it < NR_; it++) {
        int w = tid >> 5, lane = tid & 31;
        if (w < R_) {
            float v0 = logits[w][lane];
            float v1 = logits[w][lane + 32];
            float v2 = logits[w][lane + 64];
            float v3 = logits[w][lane + 96];
            float mx = fmaxf(fmaxf(v0, v1), fmaxf(v2, v3));
#pragma unroll
            for (int off = 16; off; off >>= 1)
                mx = fmaxf(mx, __shfl_xor_sync(0xFFFFFFFFu, mx, off));
            float e0 = expf(v0 - mx), e1 = expf(v1 - mx);
            float e2 = expf(v2 - mx), e3 = expf(v3 - mx);
            float s = e0 + e1 + e2 + e3;
#pragma unroll
            for (int off = 16; off; off >>= 1)
                s += __shfl_xor_sync(0xFFFFFFFFu, s, off);
            float inv = 1.f / s;
            route[w][lane]      = e0 * inv;
            route[w][lane + 32] = e1 * inv;
            route[w][lane + 64] = e2 * inv;
            route[w][lane + 96] = e3 * inv;
        }
        __syncthreads();

        for (int idx = tid; idx < SC_ * OA_; idx += 256) {
            int c = idx >> 4, o = idx & 15;
            float s = 0.f;
#pragma unroll
            for (int r = 0; r < R_; r++) {
                size_t vi = ((size_t)r * SC_ + c) * OA_ + o;
                s = fmaf(route[r][c], vb[vi] + vb2[vi], s);
            }
            act[idx] = s;
        }
        __syncthreads();

        if (tid < SC_) {
            float n2 = 0.f;
#pragma unroll
            for (int o = 0; o < OA_; o++) {
                float v = act[tid * OA_ + o];
                n2 = fmaf(v, v, n2);
            }
            fac[tid] = sqrtf(n2) / (1.f + n2);
        }
        __syncthreads();
        for (int idx = tid; idx < SC_ * OA_; idx += 256)
            act[idx] *= fac[idx >> 4];
        __syncthreads();

        if (it < NR_ - 1) {
            for (int idx = tid; idx < R_ * SC_; idx += 256) {
                int r = idx >> 7, c = idx & 127;
                float d = 0.f;
#pragma unroll
                for (int o = 0; o < OA_; o++) {
                    size_t vi = ((size_t)r * SC_ + c) * OA_ + o;
                    d = fmaf(vb[vi] + vb2[vi], act[c * OA_ + o], d);
                }
                logits[r][c] += d;
            }
            __syncthreads();
        }
    }

    if (tid < SC_) {
        float n2 = 0.f;
#pragma unroll
        for (int o = 0; o < OA_; o++) {
            float v = act[tid * OA_ + o];
            n2 = fmaf(v, v, n2);
        }
        out[(long)b * SC_ + tid] = sqrtf(n2);
    }
}

// ===========================================================================
// Host: tensor-map construction (driver entry point; no -lcuda link needed)
// ===========================================================================
typedef CUresult (CUDAAPI *PFN_encodeTiled)(
    CUtensorMap*, CUtensorMapDataType, cuuint32_t, void*,
    const cuuint64_t*, const cuuint64_t*, const cuuint32_t*, const cuuint32_t*,
    CUtensorMapInterleave, CUtensorMapSwizzle, CUtensorMapL2promotion,
    CUtensorMapFloatOOBfill);

extern "C" void kernel_launch(void* const* d_in, const int* in_sizes, int n_in,
                              void* d_out, int out_size)
{
    const float* x   = (const float*)d_in[0];  // [B,T,U2]
    const float* WS1 = (const float*)d_in[1];  // [R,DA,U2]
    const float* WS2 = (const float*)d_in[2];  // [R,U2,DA]
    const float* CW  = (const float*)d_in[3];  // [R,U2,SC*OA]
    float* out = (float*)d_out;                // [B,SC]

    __half *xh, *w1h, *w2h, *hbar;
    float *m, *votes;
    unsigned char* dtm;
    cudaGetSymbolAddress((void**)&xh,    g_xh);
    cudaGetSymbolAddress((void**)&w1h,   g_w1h);
    cudaGetSymbolAddress((void**)&w2h,   g_w2h);
    cudaGetSymbolAddress((void**)&hbar,  g_hbar);
    cudaGetSymbolAddress((void**)&m,     g_m);
    cudaGetSymbolAddress((void**)&votes, g_votes);
    cudaGetSymbolAddress((void**)&dtm,   g_tmaps);

    // Tensor maps (deterministic; same every call).
    PFN_encodeTiled enc = nullptr;
    cudaDriverEntryPointQueryResult qr;
    cudaGetDriverEntryPoint("cuTensorMapEncodeTiled", (void**)&enc,
                            cudaEnableDefault, &qr);
    static CUtensorMap h_tm[2];
    // [0] WS1 fp16: 2D [U2 cols, R*DA rows], box 64x256, SW128
    {
        cuuint64_t dims[2] = {U2_, (uint64_t)R_ * DA_};
        cuuint64_t strides[1] = {(uint64_t)U2_ * 2};
        cuuint32_t box[2] = {64, 256};
        cuuint32_t es[2] = {1, 1};
        enc(&h_tm[0], CU_TENSOR_MAP_DATA_TYPE_FLOAT16, 2, (void*)w1h,
            dims, strides, box, es,
            CU_TENSOR_MAP_INTERLEAVE_NONE, CU_TENSOR_MAP_SWIZZLE_128B,
            CU_TENSOR_MAP_L2_PROMOTION_L2_128B,
            CU_TENSOR_MAP_FLOAT_OOB_FILL_NONE);
    }
    // [1] WS2 fp16: 3D [DA cols, U2 rows, R planes], box 64x128x1, SW128
    {
        cuuint64_t dims[3] = {DA_, U2_, R_};
        cuuint64_t strides[2] = {(uint64_t)DA_ * 2, (uint64_t)U2_ * DA_ * 2};
        cuuint32_t box[3] = {64, 128, 1};
        cuuint32_t es[3] = {1, 1, 1};
        enc(&h_tm[1], CU_TENSOR_MAP_DATA_TYPE_FLOAT16, 3, (void*)w2h,
            dims, strides, box, es,
            CU_TENSOR_MAP_INTERLEAVE_NONE, CU_TENSOR_MAP_SWIZZLE_128B,
            CU_TENSOR_MAP_L2_PROMOTION_L2_128B,
            CU_TENSOR_MAP_FLOAT_OOB_FILL_NONE);
    }
    cudaMemcpyAsync(dtm, h_tm, sizeof(h_tm), cudaMemcpyHostToDevice, 0);

    cudaFuncSetAttribute(gemm_a,
                         cudaFuncAttributeMaxDynamicSharedMemorySize, GEMM_DSMEM);
    cudaFuncSetAttribute(gemm_bc,
                         cudaFuncAttributeMaxDynamicSharedMemorySize, GEMM_DSMEM);

    // Convert all three inputs to fp16 in ONE launch
    {
        long nvec = NTOT_ / 8;    // 5,242,880 vec8 units
        f2h_all_kernel<<<(unsigned)((nvec + 255) / 256), 256>>>(
            x, WS1, WS2, xh, w1h, w2h);
    }

    // Stage A: hbar = relu(x @ WS1^T)  (f16; tile 128x256, 2 CTAs/SM)
    {
        dim3 grid((R_ * DA_) / 256, (B_ * T_) / 128, 1);   // (16, 256)
        gemm_a<<<grid, 256, GEMM_DSMEM>>>(dtm, xh, hbar);
    }

    // Fused B+C: tile u=128 x t=256, 2 CTAs/SM; fp16 x in epilogue.
    {
        dim3 grid(U2_ / 128, B_, R_);                      // (8, 128, 8)
        gemm_bc<<<grid, 256, GEMM_DSMEM>>>(dtm, hbar, xh, m);
    }

    // Stage D: split-K votes partials (fp32), grid (32, 2, 8)
    {
        dim3 grid((SC_ * OA_) / 64, 2, R_);
        sgemm_d<<<grid, 256>>>(m, CW, votes);
    }

    // Stage E: dynamic routing + final class logits
    routing_kernel<<<B_, 256>>>(votes, out);
}